// round 4
// baseline (speedup 1.0000x reference)
#include <cuda_runtime.h>
#include <math.h>

#define NN    1000000
#define NSEL  200000
#define NE    100000
#define MEMD  100
#define RAWD  172
#define KREAL 572           // 472 msg + 100 h
#define KP    576           // padded K for clean 16-chunks
#define NCOLS 400           // r(100) z(100) i_n(100) h_n(100)
#define NCP   448           // padded col count (7 blocks of 64)

// ---- scratch (static __device__, allocation-free) ----
__device__ unsigned long long g_key[NSEL];
__device__ float g_X[(size_t)NSEL * KP];       // [N, 576]  row = [msg(472) | h(100) | pad]
__device__ float g_WcT[(size_t)KP * NCP];      // [576, 448] transposed combined weight
__device__ float g_G[(size_t)NSEL * NCOLS];    // [N, 400]  gate pre-activations
__device__ float g_bc[NCOLS];

// ---------------- kernel 0: init keys ----------------
__global__ void k_init() {
    int i = blockIdx.x * blockDim.x + threadIdx.x;
    if (i < NSEL) g_key[i] = 0ULL;
}

// ---------------- kernel 1: last aggregation ----------------
__global__ void k_aggr(const int* __restrict__ loc_s, const int* __restrict__ t_s,
                       const int* __restrict__ loc_d, const int* __restrict__ t_d) {
    int i = blockIdx.x * blockDim.x + threadIdx.x;
    if (i >= 2 * NE) return;
    int loc, t;
    if (i < NE) { loc = loc_s[i]; t = t_s[i]; }
    else        { loc = loc_d[i - NE]; t = t_d[i - NE]; }
    unsigned long long key =
        ((unsigned long long)(unsigned int)(t + 1) << 32) | (unsigned int)i;
    atomicMax(&g_key[loc], key);
}

// ---------------- kernel 2: combined weight prep ----------------
// WcT[k][j]: j<200 -> [W_ih | W_hh] rows j (r,z merged)
//            200<=j<300 -> i_n: W_ih row j, zeros for k>=472
//            300<=j<400 -> h_n: W_hh row j-100, zeros for k<472
__global__ void k_prep(const float* __restrict__ W_ih, const float* __restrict__ W_hh,
                       const float* __restrict__ b_ih, const float* __restrict__ b_hh) {
    int idx = blockIdx.x * blockDim.x + threadIdx.x;
    int total = KP * NCP;
    if (idx < total) {
        int k = idx / NCP;
        int j = idx % NCP;
        float v = 0.f;
        if (k < KREAL && j < NCOLS) {
            if (j < 200) {
                v = (k < 472) ? W_ih[(size_t)j * 472 + k] : W_hh[(size_t)j * 100 + (k - 472)];
            } else if (j < 300) {
                if (k < 472) v = W_ih[(size_t)j * 472 + k];
            } else {
                if (k >= 472) v = W_hh[(size_t)(j - 100) * 100 + (k - 472)];
            }
        }
        g_WcT[idx] = v;
    }
    if (idx < NCOLS) {
        float b;
        if (idx < 200)      b = b_ih[idx] + b_hh[idx];
        else if (idx < 300) b = b_ih[idx];
        else                b = b_hh[idx - 100];
        g_bc[idx] = b;
    }
}

// ---------------- kernel 3: build X rows + new_last_update ----------------
__global__ void k_build(const float* __restrict__ memory, const int* __restrict__ last_update,
                        const int* __restrict__ n_id,
                        const int* __restrict__ dst_s, const int* __restrict__ t_s,
                        const float* __restrict__ raw_s,
                        const int* __restrict__ dst_d, const int* __restrict__ t_d,
                        const float* __restrict__ raw_d,
                        const float* __restrict__ time_w, const float* __restrict__ time_b,
                        float* __restrict__ out_lu) {
    int gwarp = (blockIdx.x * blockDim.x + threadIdx.x) >> 5;
    int lane  = threadIdx.x & 31;
    if (gwarp >= NSEL) return;

    int g = n_id[gwarp];
    unsigned long long key = g_key[gwarp];
    int lu = last_update[g];
    bool valid = (key != 0ULL);

    int dst = 0, t = 0;
    const float* raw = raw_s;           // dummy, unread when invalid
    if (valid) {
        unsigned int e = (unsigned int)key;
        t = (int)(key >> 32) - 1;
        if (e < NE) { dst = dst_s[e];        raw = raw_s + (size_t)e * RAWD; }
        else        { unsigned int e2 = e - NE; dst = dst_d[e2]; raw = raw_d + (size_t)e2 * RAWD; }
    }
    if (out_lu && lane == 0) {
        int nl = valid ? max(lu, t) : lu;
        out_lu[gwarp] = (float)nl;
    }

    float* X = g_X + (size_t)gwarp * KP;
    float t_rel = (float)(t - lu);
    const float* hm = memory + (size_t)g * MEMD;
    const float* dm = memory + (size_t)dst * MEMD;

    for (int c = lane; c < MEMD; c += 32) {
        float hv = hm[c];
        X[472 + c] = hv;                                  // h part: always
        X[c]       = valid ? hv : 0.f;                    // z_src
        X[100 + c] = valid ? dm[c] : 0.f;                 // z_dst
        X[372 + c] = valid ? cosf(t_rel * time_w[c] + time_b[c]) : 0.f;  // time enc
    }
    for (int c = lane; c < RAWD; c += 32)
        X[200 + c] = valid ? raw[c] : 0.f;
    for (int c = KREAL + lane; c < KP; c += 32)
        X[c] = 0.f;                                       // K pad
}

// ---------------- kernel 4: SGEMM  G[N,400] = X[N,576] @ WcT[576,448(<=400 kept)] ----------------
// 64x64 tile, 16x16 threads, 4x4 per thread, K-chunk 16.
__global__ __launch_bounds__(256) void k_gemm() {
    __shared__ float As[16 * 64];   // [k][row]
    __shared__ float Bs[16 * 64];   // [k][col]

    int tx = threadIdx.x, ty = threadIdx.y;
    int tid = ty * 16 + tx;
    size_t row0 = (size_t)blockIdx.x * 64;
    int    c0   = blockIdx.y * 64;

    float acc[4][4];
#pragma unroll
    for (int i = 0; i < 4; i++)
#pragma unroll
        for (int j = 0; j < 4; j++) acc[i][j] = 0.f;

    int a_r  = tid >> 2;            // 0..63
    int a_kq = (tid & 3) * 4;       // 0,4,8,12
    int b_k  = tid >> 4;            // 0..15
    int b_c  = (tid & 15) * 4;      // 0..60

    for (int kk = 0; kk < KP; kk += 16) {
        float4 av = *(const float4*)&g_X[(row0 + a_r) * KP + kk + a_kq];
        As[(a_kq + 0) * 64 + a_r] = av.x;
        As[(a_kq + 1) * 64 + a_r] = av.y;
        As[(a_kq + 2) * 64 + a_r] = av.z;
        As[(a_kq + 3) * 64 + a_r] = av.w;
        *(float4*)&Bs[b_k * 64 + b_c] =
            *(const float4*)&g_WcT[(size_t)(kk + b_k) * NCP + c0 + b_c];
        __syncthreads();
#pragma unroll
        for (int k = 0; k < 16; k++) {
            float4 a = *(const float4*)&As[k * 64 + ty * 4];
            float4 b = *(const float4*)&Bs[k * 64 + tx * 4];
            float ar[4] = {a.x, a.y, a.z, a.w};
            float br[4] = {b.x, b.y, b.z, b.w};
#pragma unroll
            for (int i = 0; i < 4; i++)
#pragma unroll
                for (int j = 0; j < 4; j++) acc[i][j] += ar[i] * br[j];
        }
        __syncthreads();
    }

#pragma unroll
    for (int i = 0; i < 4; i++) {
        size_t r = row0 + ty * 4 + i;
#pragma unroll
        for (int j = 0; j < 4; j++) {
            int col = c0 + tx * 4 + j;
            if (col < NCOLS) g_G[r * NCOLS + col] = acc[i][j];
        }
    }
}

// ---------------- kernel 5: GRU gates + output ----------------
__global__ void k_gru(float* __restrict__ out_mem) {
    int idx = blockIdx.x * blockDim.x + threadIdx.x;
    if (idx >= NSEL * MEMD) return;
    int i = idx / MEMD;
    int j = idx - i * MEMD;
    const float* G = g_G + (size_t)i * NCOLS;
    float r  = 1.f / (1.f + expf(-(G[j]       + g_bc[j])));
    float z  = 1.f / (1.f + expf(-(G[100 + j] + g_bc[100 + j])));
    float in_ = G[200 + j] + g_bc[200 + j];
    float hn  = G[300 + j] + g_bc[300 + j];
    float n = tanhf(in_ + r * hn);
    float h = g_X[(size_t)i * KP + 472 + j];
    out_mem[idx] = (1.f - z) * n + z * h;
}

// ---------------- launch ----------------
extern "C" void kernel_launch(void* const* d_in, const int* in_sizes, int n_in,
                              void* d_out, int out_size) {
    const float* memory      = (const float*)d_in[0];
    const int*   last_update = (const int*)  d_in[1];
    const int*   n_id        = (const int*)  d_in[2];
    const int*   loc_s       = (const int*)  d_in[3];
    const int*   dst_s       = (const int*)  d_in[4];
    const int*   t_s         = (const int*)  d_in[5];
    const float* raw_msg_s   = (const float*)d_in[6];
    const int*   loc_d       = (const int*)  d_in[7];
    const int*   dst_d       = (const int*)  d_in[8];
    const int*   t_d         = (const int*)  d_in[9];
    const float* raw_msg_d   = (const float*)d_in[10];
    const float* time_w      = (const float*)d_in[11];
    const float* time_b      = (const float*)d_in[12];
    const float* W_ih        = (const float*)d_in[13];
    const float* W_hh        = (const float*)d_in[14];
    const float* b_ih        = (const float*)d_in[15];
    const float* b_hh        = (const float*)d_in[16];

    float* out_mem = (float*)d_out;
    float* out_lu  = (out_size >= NSEL * MEMD + NSEL) ? out_mem + (size_t)NSEL * MEMD
                                                      : nullptr;

    k_init<<<(NSEL + 255) / 256, 256>>>();
    k_aggr<<<(2 * NE + 255) / 256, 256>>>(loc_s, t_s, loc_d, t_d);
    k_prep<<<(KP * NCP + 255) / 256, 256>>>(W_ih, W_hh, b_ih, b_hh);
    k_build<<<NSEL / 8, 256>>>(memory, last_update, n_id,
                               dst_s, t_s, raw_msg_s,
                               dst_d, t_d, raw_msg_d,
                               time_w, time_b, out_lu);
    k_gemm<<<dim3(NSEL / 64, (NCP) / 64), dim3(16, 16)>>>();
    k_gru<<<(NSEL * MEMD + 255) / 256, 256>>>(out_mem);
}

// round 7
// speedup vs baseline: 2.2063x; 2.2063x over previous
#include <cuda_runtime.h>
#include <cuda_bf16.h>
#include <math.h>
#include <cstdint>

#define NSEL  200000
#define NE    100000
#define MEMD  100
#define RAWD  172
#define KREAL 572           // 472 msg + 100 h
#define KP    576           // padded K (9 chunks of 64)
#define NCP   416           // padded interleaved cols (4*100 -> 416)
#define KCHUNK 64
#define NKCH   9

// ---- scratch (static __device__, allocation-free) ----
__device__ unsigned long long g_key[NSEL];
__device__ __nv_bfloat16 g_Xhi[(size_t)NSEL * KP];
__device__ __nv_bfloat16 g_Xlo[(size_t)NSEL * KP];
__device__ __nv_bfloat16 g_Bhi[(size_t)NCP * KP];   // gate-interleaved cols
__device__ __nv_bfloat16 g_Blo[(size_t)NCP * KP];
__device__ float g_bc4[NCP];                         // interleaved biases

// ---------------- kernel 0: init keys ----------------
__global__ void k_init() {
    int i = blockIdx.x * blockDim.x + threadIdx.x;
    if (i < NSEL) g_key[i] = 0ULL;
}

// ---------------- kernel 1: last aggregation ----------------
__global__ void k_aggr(const int* __restrict__ loc_s, const int* __restrict__ t_s,
                       const int* __restrict__ loc_d, const int* __restrict__ t_d) {
    int i = blockIdx.x * blockDim.x + threadIdx.x;
    if (i >= 2 * NE) return;
    int loc, t;
    if (i < NE) { loc = loc_s[i]; t = t_s[i]; }
    else        { loc = loc_d[i - NE]; t = t_d[i - NE]; }
    unsigned long long key =
        ((unsigned long long)(unsigned int)(t + 1) << 32) | (unsigned int)i;
    atomicMax(&g_key[loc], key);
}

// ---------------- kernel 2: weight prep (interleaved, bf16 hi/lo) ------------
// col' = 4*j + gate, gate: 0=r, 1=z, 2=i_n, 3=h_n.  K-major rows of length KP.
__global__ void k_prep(const float* __restrict__ W_ih, const float* __restrict__ W_hh,
                       const float* __restrict__ b_ih, const float* __restrict__ b_hh) {
    int idx = blockIdx.x * blockDim.x + threadIdx.x;
    if (idx < NCP * KP) {
        int col = idx / KP;
        int k   = idx % KP;
        float v = 0.f;
        if (col < 400 && k < KREAL) {
            int j = col >> 2, gt = col & 3;
            if (gt == 0)
                v = (k < 472) ? W_ih[(size_t)j * 472 + k] : W_hh[(size_t)j * 100 + (k - 472)];
            else if (gt == 1)
                v = (k < 472) ? W_ih[(size_t)(100 + j) * 472 + k]
                              : W_hh[(size_t)(100 + j) * 100 + (k - 472)];
            else if (gt == 2)
                v = (k < 472) ? W_ih[(size_t)(200 + j) * 472 + k] : 0.f;
            else
                v = (k >= 472) ? W_hh[(size_t)(200 + j) * 100 + (k - 472)] : 0.f;
        }
        __nv_bfloat16 h = __float2bfloat16(v);
        g_Bhi[idx] = h;
        g_Blo[idx] = __float2bfloat16(v - __bfloat162float(h));
    }
    if (idx < NCP) {
        float b = 0.f;
        if (idx < 400) {
            int j = idx >> 2, gt = idx & 3;
            if (gt == 0)      b = b_ih[j] + b_hh[j];
            else if (gt == 1) b = b_ih[100 + j] + b_hh[100 + j];
            else if (gt == 2) b = b_ih[200 + j];
            else              b = b_hh[200 + j];
        }
        g_bc4[idx] = b;
    }
}

// ---------------- kernel 3: build X rows (bf16 hi/lo) + new_last_update ------
__device__ __forceinline__ void putx(size_t idx, float v) {
    __nv_bfloat16 h = __float2bfloat16(v);
    g_Xhi[idx] = h;
    g_Xlo[idx] = __float2bfloat16(v - __bfloat162float(h));
}

__global__ void k_build(const float* __restrict__ memory, const int* __restrict__ last_update,
                        const int* __restrict__ n_id,
                        const int* __restrict__ dst_s, const int* __restrict__ t_s,
                        const float* __restrict__ raw_s,
                        const int* __restrict__ dst_d, const int* __restrict__ t_d,
                        const float* __restrict__ raw_d,
                        const float* __restrict__ time_w, const float* __restrict__ time_b,
                        float* __restrict__ out_lu) {
    int gwarp = (blockIdx.x * blockDim.x + threadIdx.x) >> 5;
    int lane  = threadIdx.x & 31;
    if (gwarp >= NSEL) return;

    int g = n_id[gwarp];
    unsigned long long key = g_key[gwarp];
    int lu = last_update[g];
    bool valid = (key != 0ULL);

    int dst = 0, t = 0;
    const float* raw = raw_s;
    if (valid) {
        unsigned int e = (unsigned int)key;
        t = (int)(key >> 32) - 1;
        if (e < NE) { dst = dst_s[e]; raw = raw_s + (size_t)e * RAWD; }
        else        { unsigned int e2 = e - NE; dst = dst_d[e2]; raw = raw_d + (size_t)e2 * RAWD; }
    }
    if (out_lu && lane == 0) {
        int nl = valid ? max(lu, t) : lu;
        out_lu[gwarp] = (float)nl;
    }

    size_t base = (size_t)gwarp * KP;
    float t_rel = (float)(t - lu);
    const float* hm = memory + (size_t)g * MEMD;
    const float* dm = memory + (size_t)dst * MEMD;

    for (int c = lane; c < MEMD; c += 32) {
        float hv = hm[c];
        putx(base + 472 + c, hv);                               // h: always
        putx(base + c,       valid ? hv : 0.f);                 // z_src
        putx(base + 100 + c, valid ? dm[c] : 0.f);              // z_dst
        putx(base + 372 + c, valid ? cosf(t_rel * time_w[c] + time_b[c]) : 0.f);
    }
    for (int c = lane; c < RAWD; c += 32)
        putx(base + 200 + c, valid ? raw[c] : 0.f);
    for (int c = KREAL + lane; c < KP; c += 32) {
        g_Xhi[base + c] = __float2bfloat16(0.f);
        g_Xlo[base + c] = __float2bfloat16(0.f);
    }
}

// ---------------- kernel 4: mma.sync split-bf16 GEMM + fused GRU epilogue ----
// CTA tile: 128 M x 208 N (grid.y=2 covers 416 padded cols). 8 warps: 4(M)x2(N),
// warp tile 32x104 = 2 m16 x 13 n8 fragments. 3 products per k16 step.
// SMEM: 2 stages of [Ahi|Alo|Bhi|Blo], rows padded to 72 bf16 (144B) -> conflict-free.
#define A_ROWB 144
#define OF_AHI 0
#define OF_ALO 18432
#define OF_BHI 36864
#define OF_BLO 66816
#define STAGE  96768
#define SMEM_TOT (2 * STAGE)

__device__ __forceinline__ uint32_t smem_u32(const void* p) {
    uint32_t a;
    asm("{ .reg .u64 t; cvta.to.shared.u64 t, %1; cvt.u32.u64 %0, t; }" : "=r"(a) : "l"(p));
    return a;
}
__device__ __forceinline__ void cpa16(uint32_t saddr, const void* gaddr) {
    asm volatile("cp.async.cg.shared.global [%0], [%1], 16;" :: "r"(saddr), "l"(gaddr));
}
__device__ __forceinline__ uint32_t lds32(uint32_t a) {
    uint32_t v;
    asm volatile("ld.shared.b32 %0, [%1];" : "=r"(v) : "r"(a));
    return v;
}
#define MMA(d, a0, a1, a2, a3, b0, b1)                                          \
    asm volatile("mma.sync.aligned.m16n8k16.row.col.f32.bf16.bf16.f32 "         \
                 "{%0,%1,%2,%3},{%4,%5,%6,%7},{%8,%9},{%0,%1,%2,%3};"           \
                 : "+f"(d[0]), "+f"(d[1]), "+f"(d[2]), "+f"(d[3])               \
                 : "r"(a0), "r"(a1), "r"(a2), "r"(a3), "r"(b0), "r"(b1))

__global__ __launch_bounds__(256, 1)
void k_gemm(const float* __restrict__ memory, const int* __restrict__ n_id,
            float* __restrict__ out) {
    extern __shared__ char sm[];
    const uint32_t smb = smem_u32(sm);
    const int tid = threadIdx.x;
    const int wid = tid >> 5, lane = tid & 31;
    const int g  = lane >> 2, t4 = lane & 3;
    const int wm0 = (wid & 3) * 32;
    const int wn0 = (wid >> 2) * 104;
    const size_t row0 = (size_t)blockIdx.x * 128;
    const int cy = blockIdx.y;

    float acc[2][13][4];
#pragma unroll
    for (int mt = 0; mt < 2; mt++)
#pragma unroll
        for (int nt = 0; nt < 13; nt++)
#pragma unroll
            for (int q = 0; q < 4; q++) acc[mt][nt][q] = 0.f;

    auto load_chunk = [&](int c) {
        int kk = c * KCHUNK;
        uint32_t sb = smb + (c & 1) * STAGE;
#pragma unroll
        for (int q = tid; q < 1024; q += 256) {       // A: 128 rows x 8 u4
            int r = q >> 3, u = q & 7;
            size_t gr = row0 + r;
            if (gr >= NSEL) gr = NSEL - 1;            // clamp: garbage rows never stored
            size_t go = (gr * KP + kk) * 2 + u * 16;
            uint32_t so = (uint32_t)(r * A_ROWB + u * 16);
            cpa16(sb + OF_AHI + so, (const char*)g_Xhi + go);
            cpa16(sb + OF_ALO + so, (const char*)g_Xlo + go);
        }
        for (int q = tid; q < 1664; q += 256) {       // B: 208 rows x 8 u4
            int r = q >> 3, u = q & 7;
            size_t go = ((size_t)(cy * 208 + r) * KP + kk) * 2 + u * 16;
            uint32_t so = (uint32_t)(r * A_ROWB + u * 16);
            cpa16(sb + OF_BHI + so, (const char*)g_Bhi + go);
            cpa16(sb + OF_BLO + so, (const char*)g_Blo + go);
        }
        asm volatile("cp.async.commit_group;" ::: "memory");
    };

    load_chunk(0);
    for (int c = 0; c < NKCH; c++) {
        if (c + 1 < NKCH) {
            load_chunk(c + 1);
            asm volatile("cp.async.wait_group 1;" ::: "memory");
        } else {
            asm volatile("cp.async.wait_group 0;" ::: "memory");
        }
        __syncthreads();

        uint32_t sb = smb + (c & 1) * STAGE;
#pragma unroll
        for (int ks = 0; ks < 4; ks++) {
            const uint32_t kb2 = (uint32_t)((ks * 16 + t4 * 2) * 2);
            uint32_t ah[2][4], al[2][4];
#pragma unroll
            for (int mt = 0; mt < 2; mt++) {
                uint32_t ar = sb + (uint32_t)((wm0 + mt * 16 + g) * A_ROWB) + kb2;
                ah[mt][0] = lds32(ar + OF_AHI);
                ah[mt][1] = lds32(ar + OF_AHI + 8 * A_ROWB);
                ah[mt][2] = lds32(ar + OF_AHI + 16);
                ah[mt][3] = lds32(ar + OF_AHI + 8 * A_ROWB + 16);
                al[mt][0] = lds32(ar + OF_ALO);
                al[mt][1] = lds32(ar + OF_ALO + 8 * A_ROWB);
                al[mt][2] = lds32(ar + OF_ALO + 16);
                al[mt][3] = lds32(ar + OF_ALO + 8 * A_ROWB + 16);
            }
#pragma unroll
            for (int nt = 0; nt < 13; nt++) {
                uint32_t br = sb + (uint32_t)((wn0 + nt * 8 + g) * A_ROWB) + kb2;
                uint32_t bh0 = lds32(br + OF_BHI);
                uint32_t bh1 = lds32(br + OF_BHI + 16);
                uint32_t bl0 = lds32(br + OF_BLO);
                uint32_t bl1 = lds32(br + OF_BLO + 16);
#pragma unroll
                for (int mt = 0; mt < 2; mt++) {
                    MMA(acc[mt][nt], ah[mt][0], ah[mt][1], ah[mt][2], ah[mt][3], bh0, bh1);
                    MMA(acc[mt][nt], ah[mt][0], ah[mt][1], ah[mt][2], ah[mt][3], bl0, bl1);
                    MMA(acc[mt][nt], al[mt][0], al[mt][1], al[mt][2], al[mt][3], bh0, bh1);
                }
            }
        }
        __syncthreads();
    }

    // ---- stage h tile (52 cols this CTA needs) into smem ----
    int*   sNid = (int*)sm;
    float* sH   = (float*)(sm + 512);
    for (int i = tid; i < 128; i += 256) {
        size_t m = row0 + i;
        sNid[i] = (m < NSEL) ? n_id[m] : 0;
    }
    __syncthreads();
    for (int q = tid; q < 128 * 52; q += 256) {
        int r = q / 52, jj = q - r * 52;
        int col = cy * 52 + jj;
        float v = 0.f;
        if (row0 + r < NSEL && col < MEMD)
            v = memory[(size_t)sNid[r] * MEMD + col];
        sH[r * 53 + jj] = v;
    }
    __syncthreads();

    // ---- fused GRU epilogue ----
    const int jbase = cy * 52 + (wn0 >> 2);
#pragma unroll
    for (int mt = 0; mt < 2; mt++) {
#pragma unroll
        for (int nt = 0; nt < 13; nt++) {
            int colp = cy * 208 + wn0 + nt * 8 + t4 * 2;
            float b0 = g_bc4[colp], b1 = g_bc4[colp + 1];
            float c0 = acc[mt][nt][0] + b0, c1 = acc[mt][nt][1] + b1;
            float c2 = acc[mt][nt][2] + b0, c3 = acc[mt][nt][3] + b1;
            float d0 = __shfl_xor_sync(0xffffffffu, c0, 1);
            float d1 = __shfl_xor_sync(0xffffffffu, c1, 1);
            float d2 = __shfl_xor_sync(0xffffffffu, c2, 1);
            float d3 = __shfl_xor_sync(0xffffffffu, c3, 1);
            if (!(t4 & 1)) {                       // even t4 holds (r,z); partner (in,hn)
                int j = jbase + 2 * nt + (t4 >> 1);
                if (j < MEMD) {
                    int jj = j - cy * 52;
                    int rl = wm0 + mt * 16 + g;
                    size_t m = row0 + rl;
                    if (m < NSEL) {
                        float r_ = 1.f / (1.f + expf(-c0));
                        float z_ = 1.f / (1.f + expf(-c1));
                        float n_ = tanhf(d0 + r_ * d1);
                        out[m * MEMD + j] = (1.f - z_) * n_ + z_ * sH[rl * 53 + jj];
                    }
                    if (m + 8 < NSEL) {
                        float r_ = 1.f / (1.f + expf(-c2));
                        float z_ = 1.f / (1.f + expf(-c3));
                        float n_ = tanhf(d2 + r_ * d3);
                        out[(m + 8) * MEMD + j] = (1.f - z_) * n_ + z_ * sH[(rl + 8) * 53 + jj];
                    }
                }
            }
        }
    }
}

// ---------------- launch ----------------
extern "C" void kernel_launch(void* const* d_in, const int* in_sizes, int n_in,
                              void* d_out, int out_size) {
    const float* memory      = (const float*)d_in[0];
    const int*   last_update = (const int*)  d_in[1];
    const int*   n_id        = (const int*)  d_in[2];
    const int*   loc_s       = (const int*)  d_in[3];
    const int*   dst_s       = (const int*)  d_in[4];
    const int*   t_s         = (const int*)  d_in[5];
    const float* raw_msg_s   = (const float*)d_in[6];
    const int*   loc_d       = (const int*)  d_in[7];
    const int*   dst_d       = (const int*)  d_in[8];
    const int*   t_d         = (const int*)  d_in[9];
    const float* raw_msg_d   = (const float*)d_in[10];
    const float* time_w      = (const float*)d_in[11];
    const float* time_b      = (const float*)d_in[12];
    const float* W_ih        = (const float*)d_in[13];
    const float* W_hh        = (const float*)d_in[14];
    const float* b_ih        = (const float*)d_in[15];
    const float* b_hh        = (const float*)d_in[16];

    float* out_mem = (float*)d_out;
    float* out_lu  = (out_size >= NSEL * MEMD + NSEL) ? out_mem + (size_t)NSEL * MEMD
                                                      : nullptr;

    cudaFuncSetAttribute(k_gemm, cudaFuncAttributeMaxDynamicSharedMemorySize, SMEM_TOT);

    k_init<<<(NSEL + 255) / 256, 256>>>();
    k_aggr<<<(2 * NE + 255) / 256, 256>>>(loc_s, t_s, loc_d, t_d);
    k_prep<<<(NCP * KP + 255) / 256, 256>>>(W_ih, W_hh, b_ih, b_hh);
    k_build<<<NSEL / 8, 256>>>(memory, last_update, n_id,
                               dst_s, t_s, raw_msg_s,
                               dst_d, t_d, raw_msg_d,
                               time_w, time_b, out_lu);
    k_gemm<<<dim3((NSEL + 127) / 128, 2), 256, SMEM_TOT>>>(memory, n_id, out_mem);
}

// round 9
// speedup vs baseline: 2.4695x; 1.1193x over previous
#include <cuda_runtime.h>
#include <cuda_bf16.h>
#include <math.h>
#include <cstdint>

#define NSEL  200000
#define NE    100000
#define MEMD  100
#define RAWD  172
#define KREAL 572           // 472 msg + 100 h
#define KP    576           // padded K (9 chunks of 64)
#define NCP   416           // padded interleaved cols (4*100 -> 416)
#define KCHUNK 64
#define NKCH   9

// ---- scratch (static __device__, allocation-free) ----
__device__ unsigned long long g_key[NSEL];
__device__ __nv_bfloat16 g_Xhi[(size_t)NSEL * KP];
__device__ __nv_bfloat16 g_Xlo[(size_t)NSEL * KP];
__device__ __nv_bfloat16 g_Bhi[(size_t)NCP * KP];   // gate-interleaved cols
__device__ __nv_bfloat16 g_Blo[(size_t)NCP * KP];
__device__ float g_bc4[NCP];                         // interleaved biases
__device__ int g_cnt0, g_cnt1;                      // valid / invalid counters
__device__ int g_perm[NSEL];                        // orig node -> compacted row
__device__ int g_rowmap[NSEL];                      // compacted row -> orig node

// ---------------- kernel 0: init keys + counters ----------------
__global__ void k_init() {
    int i = blockIdx.x * blockDim.x + threadIdx.x;
    if (i < NSEL) g_key[i] = 0ULL;
    if (i == 0) { g_cnt0 = 0; g_cnt1 = 0; }
}

// ---------------- kernel 1: last aggregation ----------------
__global__ void k_aggr(const int* __restrict__ loc_s, const int* __restrict__ t_s,
                       const int* __restrict__ loc_d, const int* __restrict__ t_d) {
    int i = blockIdx.x * blockDim.x + threadIdx.x;
    if (i >= 2 * NE) return;
    int loc, t;
    if (i < NE) { loc = loc_s[i]; t = t_s[i]; }
    else        { loc = loc_d[i - NE]; t = t_d[i - NE]; }
    unsigned long long key =
        ((unsigned long long)(unsigned int)(t + 1) << 32) | (unsigned int)i;
    atomicMax(&g_key[loc], key);
}

// ---------------- kernel 1b: partition rows (valid first, invalid at tail) ---
// NSEL is a multiple of 32, so every active warp is fully active.
__global__ void k_part() {
    int i = blockIdx.x * blockDim.x + threadIdx.x;
    if (i >= NSEL) return;
    int lane = threadIdx.x & 31;
    bool valid = (g_key[i] != 0ULL);
    unsigned mv = __ballot_sync(0xffffffffu, valid);
    int nv = __popc(mv), ni = 32 - nv;
    int bv = 0, bi = 0;
    if (lane == 0) {
        if (nv) bv = atomicAdd(&g_cnt0, nv);
        if (ni) bi = atomicAdd(&g_cnt1, ni);
    }
    bv = __shfl_sync(0xffffffffu, bv, 0);
    bi = __shfl_sync(0xffffffffu, bi, 0);
    unsigned lt = (1u << lane) - 1u;
    int p = valid ? (bv + __popc(mv & lt))
                  : (NSEL - 1 - (bi + __popc(~mv & lt)));
    g_perm[i] = p;
    g_rowmap[p] = i;
}

// ---------------- kernel 2: weight prep (interleaved, bf16 hi/lo) ------------
// col' = 4*j + gate, gate: 0=r, 1=z, 2=i_n, 3=h_n.  K-major rows of length KP.
__global__ void k_prep(const float* __restrict__ W_ih, const float* __restrict__ W_hh,
                       const float* __restrict__ b_ih, const float* __restrict__ b_hh) {
    int idx = blockIdx.x * blockDim.x + threadIdx.x;
    if (idx < NCP * KP) {
        int col = idx / KP;
        int k   = idx % KP;
        float v = 0.f;
        if (col < 400 && k < KREAL) {
            int j = col >> 2, gt = col & 3;
            if (gt == 0)
                v = (k < 472) ? W_ih[(size_t)j * 472 + k] : W_hh[(size_t)j * 100 + (k - 472)];
            else if (gt == 1)
                v = (k < 472) ? W_ih[(size_t)(100 + j) * 472 + k]
                              : W_hh[(size_t)(100 + j) * 100 + (k - 472)];
            else if (gt == 2)
                v = (k < 472) ? W_ih[(size_t)(200 + j) * 472 + k] : 0.f;
            else
                v = (k >= 472) ? W_hh[(size_t)(200 + j) * 100 + (k - 472)] : 0.f;
        }
        __nv_bfloat16 h = __float2bfloat16(v);
        g_Bhi[idx] = h;
        g_Blo[idx] = __float2bfloat16(v - __bfloat162float(h));
    }
    if (idx < NCP) {
        float b = 0.f;
        if (idx < 400) {
            int j = idx >> 2, gt = idx & 3;
            if (gt == 0)      b = b_ih[j] + b_hh[j];
            else if (gt == 1) b = b_ih[100 + j] + b_hh[100 + j];
            else if (gt == 2) b = b_ih[200 + j];
            else              b = b_hh[200 + j];
        }
        g_bc4[idx] = b;
    }
}

// ---------------- kernel 3: build X rows (compacted, bf16 hi/lo) -------------
__device__ __forceinline__ void putx(size_t idx, float v) {
    __nv_bfloat16 h = __float2bfloat16(v);
    g_Xhi[idx] = h;
    g_Xlo[idx] = __float2bfloat16(v - __bfloat162float(h));
}
__device__ __forceinline__ void putz(size_t idx) {
    g_Xhi[idx] = __float2bfloat16(0.f);
    g_Xlo[idx] = __float2bfloat16(0.f);
}

__global__ void k_build(const float* __restrict__ memory, const int* __restrict__ last_update,
                        const int* __restrict__ n_id,
                        const int* __restrict__ dst_s, const int* __restrict__ t_s,
                        const float* __restrict__ raw_s,
                        const int* __restrict__ dst_d, const int* __restrict__ t_d,
                        const float* __restrict__ raw_d,
                        const float* __restrict__ time_w, const float* __restrict__ time_b,
                        float* __restrict__ out_lu) {
    int gwarp = (blockIdx.x * blockDim.x + threadIdx.x) >> 5;
    int lane  = threadIdx.x & 31;
    if (gwarp >= NSEL) return;

    int g = n_id[gwarp];
    unsigned long long key = g_key[gwarp];
    int lu = last_update[g];
    bool valid = (key != 0ULL);

    int dst = 0, t = 0;
    const float* raw = raw_s;
    if (valid) {
        unsigned int e = (unsigned int)key;
        t = (int)(key >> 32) - 1;
        if (e < NE) { dst = dst_s[e]; raw = raw_s + (size_t)e * RAWD; }
        else        { unsigned int e2 = e - NE; dst = dst_d[e2]; raw = raw_d + (size_t)e2 * RAWD; }
    }
    if (out_lu && lane == 0) {
        int nl = valid ? max(lu, t) : lu;
        out_lu[gwarp] = (float)nl;
    }

    int p = g_perm[gwarp];
    size_t base = (size_t)p * KP;
    const float* hm = memory + (size_t)g * MEMD;

    if (valid) {
        float t_rel = (float)(t - lu);
        const float* dm = memory + (size_t)dst * MEMD;
        for (int c = lane; c < MEMD; c += 32) {
            float hv = hm[c];
            putx(base + 472 + c, hv);                 // h
            putx(base + c,       hv);                 // z_src
            putx(base + 100 + c, dm[c]);              // z_dst
            putx(base + 372 + c, cosf(t_rel * time_w[c] + time_b[c]));
        }
        for (int c = lane; c < RAWD; c += 32)
            putx(base + 200 + c, raw[c]);
        for (int c = KREAL + lane; c < KP; c += 32)
            putz(base + c);
    } else {
        // invalid rows: only chunks 7..8 (cols 448..576) are ever read by the
        // GEMM, except rows in the straddle CTA, which need full zero-fill.
        int NV = g_cnt0;
        if (p < ((NV + 127) & ~127)) {
            for (int c = lane; c < 448; c += 32) putz(base + c);
        }
        for (int c = lane; c < 24; c += 32)  putz(base + 448 + c);
        for (int c = lane; c < MEMD; c += 32) putx(base + 472 + c, hm[c]);
        for (int c = KREAL + lane; c < KP; c += 32) putz(base + c);
    }
}

// ---------------- kernel 4: mma.sync split-bf16 GEMM + fused GRU epilogue ----
// CTA tile: 128 M x 208 N (grid.y=2 covers 416 padded cols). 8 warps: 4(M)x2(N),
// warp tile 32x104 = 2 m16 x 13 n8 fragments. 3 products per k16 step.
// CTAs whose rows are all invalid (row0 >= NV) start at chunk 7 (h-block only).
#define A_ROWB 144
#define OF_AHI 0
#define OF_ALO 18432
#define OF_BHI 36864
#define OF_BLO 66816
#define STAGE  96768
#define SMEM_TOT (2 * STAGE)

__device__ __forceinline__ uint32_t smem_u32(const void* p) {
    uint32_t a;
    asm("{ .reg .u64 t; cvta.to.shared.u64 t, %1; cvt.u32.u64 %0, t; }" : "=r"(a) : "l"(p));
    return a;
}
__device__ __forceinline__ void cpa16(uint32_t saddr, const void* gaddr) {
    asm volatile("cp.async.cg.shared.global [%0], [%1], 16;" :: "r"(saddr), "l"(gaddr));
}
__device__ __forceinline__ uint32_t lds32(uint32_t a) {
    uint32_t v;
    asm volatile("ld.shared.b32 %0, [%1];" : "=r"(v) : "r"(a));
    return v;
}
#define MMA(d, a0, a1, a2, a3, b0, b1)                                          \
    asm volatile("mma.sync.aligned.m16n8k16.row.col.f32.bf16.bf16.f32 "         \
                 "{%0,%1,%2,%3},{%4,%5,%6,%7},{%8,%9},{%0,%1,%2,%3};"           \
                 : "+f"(d[0]), "+f"(d[1]), "+f"(d[2]), "+f"(d[3])               \
                 : "r"(a0), "r"(a1), "r"(a2), "r"(a3), "r"(b0), "r"(b1))

__global__ __launch_bounds__(256, 1)
void k_gemm(const float* __restrict__ memory, const int* __restrict__ n_id,
            float* __restrict__ out) {
    extern __shared__ char sm[];
    const uint32_t smb = smem_u32(sm);
    const int tid = threadIdx.x;
    const int wid = tid >> 5, lane = tid & 31;
    const int g  = lane >> 2, t4 = lane & 3;
    const int wm0 = (wid & 3) * 32;
    const int wn0 = (wid >> 2) * 104;
    const size_t row0 = (size_t)blockIdx.x * 128;
    const int cy = blockIdx.y;

    const int NV = g_cnt0;
    const int c0 = (row0 >= (size_t)NV) ? 7 : 0;

    float acc[2][13][4];
#pragma unroll
    for (int mt = 0; mt < 2; mt++)
#pragma unroll
        for (int nt = 0; nt < 13; nt++)
#pragma unroll
            for (int q = 0; q < 4; q++) acc[mt][nt][q] = 0.f;

    auto load_chunk = [&](int c) {
        int kk = c * KCHUNK;
        uint32_t sb = smb + (c & 1) * STAGE;
#pragma unroll
        for (int q = tid; q < 1024; q += 256) {       // A: 128 rows x 8 u4
            int r = q >> 3, u = q & 7;
            size_t gr = row0 + r;
            if (gr >= NSEL) gr = NSEL - 1;            // clamp: results discarded
            size_t go = (gr * KP + kk) * 2 + u * 16;
            uint32_t so = (uint32_t)(r * A_ROWB + u * 16);
            cpa16(sb + OF_AHI + so, (const char*)g_Xhi + go);
            cpa16(sb + OF_ALO + so, (const char*)g_Xlo + go);
        }
        for (int q = tid; q < 1664; q += 256) {       // B: 208 rows x 8 u4
            int r = q >> 3, u = q & 7;
            size_t go = ((size_t)(cy * 208 + r) * KP + kk) * 2 + u * 16;
            uint32_t so = (uint32_t)(r * A_ROWB + u * 16);
            cpa16(sb + OF_BHI + so, (const char*)g_Bhi + go);
            cpa16(sb + OF_BLO + so, (const char*)g_Blo + go);
        }
        asm volatile("cp.async.commit_group;" ::: "memory");
    };

    load_chunk(c0);
    for (int c = c0; c < NKCH; c++) {
        if (c + 1 < NKCH) {
            load_chunk(c + 1);
            asm volatile("cp.async.wait_group 1;" ::: "memory");
        } else {
            asm volatile("cp.async.wait_group 0;" ::: "memory");
        }
        __syncthreads();

        uint32_t sb = smb + (c & 1) * STAGE;
#pragma unroll
        for (int ks = 0; ks < 4; ks++) {
            const uint32_t kb2 = (uint32_t)((ks * 16 + t4 * 2) * 2);
            uint32_t ah[2][4], al[2][4];
#pragma unroll
            for (int mt = 0; mt < 2; mt++) {
                uint32_t ar = sb + (uint32_t)((wm0 + mt * 16 + g) * A_ROWB) + kb2;
                ah[mt][0] = lds32(ar + OF_AHI);
                ah[mt][1] = lds32(ar + OF_AHI + 8 * A_ROWB);
                ah[mt][2] = lds32(ar + OF_AHI + 16);
                ah[mt][3] = lds32(ar + OF_AHI + 8 * A_ROWB + 16);
                al[mt][0] = lds32(ar + OF_ALO);
                al[mt][1] = lds32(ar + OF_ALO + 8 * A_ROWB);
                al[mt][2] = lds32(ar + OF_ALO + 16);
                al[mt][3] = lds32(ar + OF_ALO + 8 * A_ROWB + 16);
            }
#pragma unroll
            for (int nt = 0; nt < 13; nt++) {
                uint32_t br = sb + (uint32_t)((wn0 + nt * 8 + g) * A_ROWB) + kb2;
                uint32_t bh0 = lds32(br + OF_BHI);
                uint32_t bh1 = lds32(br + OF_BHI + 16);
                uint32_t bl0 = lds32(br + OF_BLO);
                uint32_t bl1 = lds32(br + OF_BLO + 16);
#pragma unroll
                for (int mt = 0; mt < 2; mt++) {
                    MMA(acc[mt][nt], ah[mt][0], ah[mt][1], ah[mt][2], ah[mt][3], bh0, bh1);
                    MMA(acc[mt][nt], ah[mt][0], ah[mt][1], ah[mt][2], ah[mt][3], bl0, bl1);
                    MMA(acc[mt][nt], al[mt][0], al[mt][1], al[mt][2], al[mt][3], bh0, bh1);
                }
            }
        }
        __syncthreads();
    }

    // ---- stage orig ids / n_id / h tile (52 cols this CTA needs) ----
    int*   sOrig = (int*)sm;
    int*   sNid  = (int*)(sm + 512);
    float* sH    = (float*)(sm + 1024);
    for (int i = tid; i < 128; i += 256) {
        size_t pr = row0 + i;
        int o = (pr < NSEL) ? g_rowmap[pr] : 0;
        sOrig[i] = o;
        sNid[i]  = n_id[o];
    }
    __syncthreads();
    for (int q = tid; q < 128 * 52; q += 256) {
        int r = q / 52, jj = q - r * 52;
        int col = cy * 52 + jj;
        float v = 0.f;
        if (row0 + r < NSEL && col < MEMD)
            v = memory[(size_t)sNid[r] * MEMD + col];
        sH[r * 53 + jj] = v;
    }
    __syncthreads();

    // ---- fused GRU epilogue ----
    const int jbase = cy * 52 + (wn0 >> 2);
#pragma unroll
    for (int mt = 0; mt < 2; mt++) {
#pragma unroll
        for (int nt = 0; nt < 13; nt++) {
            int colp = cy * 208 + wn0 + nt * 8 + t4 * 2;
            float b0 = g_bc4[colp], b1 = g_bc4[colp + 1];
            float c0v = acc[mt][nt][0] + b0, c1v = acc[mt][nt][1] + b1;
            float c2v = acc[mt][nt][2] + b0, c3v = acc[mt][nt][3] + b1;
            float d0 = __shfl_xor_sync(0xffffffffu, c0v, 1);
            float d1 = __shfl_xor_sync(0xffffffffu, c1v, 1);
            float d2 = __shfl_xor_sync(0xffffffffu, c2v, 1);
            float d3 = __shfl_xor_sync(0xffffffffu, c3v, 1);
            if (!(t4 & 1)) {                       // even t4 holds (r,z); partner (in,hn)
                int j = jbase + 2 * nt + (t4 >> 1);
                if (j < MEMD) {
                    int jj = j - cy * 52;
                    int rl = wm0 + mt * 16 + g;
                    size_t pr = row0 + rl;
                    if (pr < NSEL) {
                        float r_ = 1.f / (1.f + expf(-c0v));
                        float z_ = 1.f / (1.f + expf(-c1v));
                        float n_ = tanhf(d0 + r_ * d1);
                        out[(size_t)sOrig[rl] * MEMD + j] =
                            (1.f - z_) * n_ + z_ * sH[rl * 53 + jj];
                    }
                    if (pr + 8 < NSEL) {
                        float r_ = 1.f / (1.f + expf(-c2v));
                        float z_ = 1.f / (1.f + expf(-c3v));
                        float n_ = tanhf(d2 + r_ * d3);
                        out[(size_t)sOrig[rl + 8] * MEMD + j] =
                            (1.f - z_) * n_ + z_ * sH[(rl + 8) * 53 + jj];
                    }
                }
            }
        }
    }
}

// ---------------- launch ----------------
extern "C" void kernel_launch(void* const* d_in, const int* in_sizes, int n_in,
                              void* d_out, int out_size) {
    const float* memory      = (const float*)d_in[0];
    const int*   last_update = (const int*)  d_in[1];
    const int*   n_id        = (const int*)  d_in[2];
    const int*   loc_s       = (const int*)  d_in[3];
    const int*   dst_s       = (const int*)  d_in[4];
    const int*   t_s         = (const int*)  d_in[5];
    const float* raw_msg_s   = (const float*)d_in[6];
    const int*   loc_d       = (const int*)  d_in[7];
    const int*   dst_d       = (const int*)  d_in[8];
    const int*   t_d         = (const int*)  d_in[9];
    const float* raw_msg_d   = (const float*)d_in[10];
    const float* time_w      = (const float*)d_in[11];
    const float* time_b      = (const float*)d_in[12];
    const float* W_ih        = (const float*)d_in[13];
    const float* W_hh        = (const float*)d_in[14];
    const float* b_ih        = (const float*)d_in[15];
    const float* b_hh        = (const float*)d_in[16];

    float* out_mem = (float*)d_out;
    float* out_lu  = (out_size >= NSEL * MEMD + NSEL) ? out_mem + (size_t)NSEL * MEMD
                                                      : nullptr;

    cudaFuncSetAttribute(k_gemm, cudaFuncAttributeMaxDynamicSharedMemorySize, SMEM_TOT);

    k_init<<<(NSEL + 255) / 256, 256>>>();
    k_aggr<<<(2 * NE + 255) / 256, 256>>>(loc_s, t_s, loc_d, t_d);
    k_part<<<(NSEL + 255) / 256, 256>>>();
    k_prep<<<(NCP * KP + 255) / 256, 256>>>(W_ih, W_hh, b_ih, b_hh);
    k_build<<<NSEL / 8, 256>>>(memory, last_update, n_id,
                               dst_s, t_s, raw_msg_s,
                               dst_d, t_d, raw_msg_d,
                               time_w, time_b, out_lu);
    k_gemm<<<dim3((NSEL + 127) / 128, 2), 256, SMEM_TOT>>>(memory, n_id, out_mem);
}

// round 11
// speedup vs baseline: 2.5311x; 1.0250x over previous
#include <cuda_runtime.h>
#include <cuda_bf16.h>
#include <math.h>
#include <cstdint>

#define NSEL  200000
#define NE    100000
#define MEMD  100
#define RAWD  172
#define KREAL 572           // 472 msg + 100 h
#define KP    576           // padded K (18 chunks of 32)
#define NCP   416           // padded interleaved cols (4*100 -> 416)
#define KCHUNK 32
#define NKCH   18

// ---- scratch (static __device__, allocation-free) ----
__device__ unsigned long long g_key[NSEL];
__device__ __nv_bfloat16 g_Xhi[(size_t)NSEL * KP];
__device__ __nv_bfloat16 g_Xlo[(size_t)NSEL * KP];
__device__ __nv_bfloat16 g_Bhi[(size_t)NCP * KP];   // gate-interleaved cols
__device__ __nv_bfloat16 g_Blo[(size_t)NCP * KP];
__device__ float g_bc4[NCP];                         // interleaved biases
__device__ int g_cnt0, g_cnt1;                      // valid / invalid counters
__device__ int g_perm[NSEL];                        // orig node -> compacted row
__device__ int g_rowmap[NSEL];                      // compacted row -> orig node

// ---------------- kernel 0: init keys + counters ----------------
__global__ void k_init() {
    int i = blockIdx.x * blockDim.x + threadIdx.x;
    if (i < NSEL) g_key[i] = 0ULL;
    if (i == 0) { g_cnt0 = 0; g_cnt1 = 0; }
}

// ---------------- kernel 1: last aggregation ----------------
__global__ void k_aggr(const int* __restrict__ loc_s, const int* __restrict__ t_s,
                       const int* __restrict__ loc_d, const int* __restrict__ t_d) {
    int i = blockIdx.x * blockDim.x + threadIdx.x;
    if (i >= 2 * NE) return;
    int loc, t;
    if (i < NE) { loc = loc_s[i]; t = t_s[i]; }
    else        { loc = loc_d[i - NE]; t = t_d[i - NE]; }
    unsigned long long key =
        ((unsigned long long)(unsigned int)(t + 1) << 32) | (unsigned int)i;
    atomicMax(&g_key[loc], key);
}

// ---------------- kernel 1b: partition rows (valid first, invalid at tail) ---
__global__ void k_part() {
    int i = blockIdx.x * blockDim.x + threadIdx.x;
    if (i >= NSEL) return;
    int lane = threadIdx.x & 31;
    bool valid = (g_key[i] != 0ULL);
    unsigned mv = __ballot_sync(0xffffffffu, valid);
    int nv = __popc(mv), ni = 32 - nv;
    int bv = 0, bi = 0;
    if (lane == 0) {
        if (nv) bv = atomicAdd(&g_cnt0, nv);
        if (ni) bi = atomicAdd(&g_cnt1, ni);
    }
    bv = __shfl_sync(0xffffffffu, bv, 0);
    bi = __shfl_sync(0xffffffffu, bi, 0);
    unsigned lt = (1u << lane) - 1u;
    int p = valid ? (bv + __popc(mv & lt))
                  : (NSEL - 1 - (bi + __popc(~mv & lt)));
    g_perm[i] = p;
    g_rowmap[p] = i;
}

// ---------------- kernel 2: weight prep (interleaved, bf16 hi/lo) ------------
__global__ void k_prep(const float* __restrict__ W_ih, const float* __restrict__ W_hh,
                       const float* __restrict__ b_ih, const float* __restrict__ b_hh) {
    int idx = blockIdx.x * blockDim.x + threadIdx.x;
    if (idx < NCP * KP) {
        int col = idx / KP;
        int k   = idx % KP;
        float v = 0.f;
        if (col < 400 && k < KREAL) {
            int j = col >> 2, gt = col & 3;
            if (gt == 0)
                v = (k < 472) ? W_ih[(size_t)j * 472 + k] : W_hh[(size_t)j * 100 + (k - 472)];
            else if (gt == 1)
                v = (k < 472) ? W_ih[(size_t)(100 + j) * 472 + k]
                              : W_hh[(size_t)(100 + j) * 100 + (k - 472)];
            else if (gt == 2)
                v = (k < 472) ? W_ih[(size_t)(200 + j) * 472 + k] : 0.f;
            else
                v = (k >= 472) ? W_hh[(size_t)(200 + j) * 100 + (k - 472)] : 0.f;
        }
        __nv_bfloat16 h = __float2bfloat16(v);
        g_Bhi[idx] = h;
        g_Blo[idx] = __float2bfloat16(v - __bfloat162float(h));
    }
    if (idx < NCP) {
        float b = 0.f;
        if (idx < 400) {
            int j = idx >> 2, gt = idx & 3;
            if (gt == 0)      b = b_ih[j] + b_hh[j];
            else if (gt == 1) b = b_ih[100 + j] + b_hh[100 + j];
            else if (gt == 2) b = b_ih[200 + j];
            else              b = b_hh[200 + j];
        }
        g_bc4[idx] = b;
    }
}

// ---------------- kernel 3: build X rows (compacted, vectorized) -------------
__device__ __forceinline__ void put4(size_t idx, float4 v) {
    __nv_bfloat162 h01 = __floats2bfloat162_rn(v.x, v.y);
    __nv_bfloat162 h23 = __floats2bfloat162_rn(v.z, v.w);
    __nv_bfloat162 l01 = __floats2bfloat162_rn(v.x - __low2float(h01),
                                               v.y - __high2float(h01));
    __nv_bfloat162 l23 = __floats2bfloat162_rn(v.z - __low2float(h23),
                                               v.w - __high2float(h23));
    uint2 uh, ul;
    uh.x = *reinterpret_cast<uint32_t*>(&h01);
    uh.y = *reinterpret_cast<uint32_t*>(&h23);
    ul.x = *reinterpret_cast<uint32_t*>(&l01);
    ul.y = *reinterpret_cast<uint32_t*>(&l23);
    *reinterpret_cast<uint2*>(g_Xhi + idx) = uh;
    *reinterpret_cast<uint2*>(g_Xlo + idx) = ul;
}
__device__ __forceinline__ void zero4(size_t idx) {
    uint2 z = make_uint2(0u, 0u);
    *reinterpret_cast<uint2*>(g_Xhi + idx) = z;
    *reinterpret_cast<uint2*>(g_Xlo + idx) = z;
}

__global__ void k_build(const float* __restrict__ memory, const int* __restrict__ last_update,
                        const int* __restrict__ n_id,
                        const int* __restrict__ dst_s, const int* __restrict__ t_s,
                        const float* __restrict__ raw_s,
                        const int* __restrict__ dst_d, const int* __restrict__ t_d,
                        const float* __restrict__ raw_d,
                        const float* __restrict__ time_w, const float* __restrict__ time_b,
                        float* __restrict__ out_lu) {
    int gwarp = (blockIdx.x * blockDim.x + threadIdx.x) >> 5;
    int lane  = threadIdx.x & 31;
    if (gwarp >= NSEL) return;

    int g = n_id[gwarp];
    unsigned long long key = g_key[gwarp];
    int lu = last_update[g];
    bool valid = (key != 0ULL);

    int dst = 0, t = 0;
    const float* raw = raw_s;
    if (valid) {
        unsigned int e = (unsigned int)key;
        t = (int)(key >> 32) - 1;
        if (e < NE) { dst = dst_s[e]; raw = raw_s + (size_t)e * RAWD; }
        else        { unsigned int e2 = e - NE; dst = dst_d[e2]; raw = raw_d + (size_t)e2 * RAWD; }
    }
    if (out_lu && lane == 0) {
        int nl = valid ? max(lu, t) : lu;
        out_lu[gwarp] = (float)nl;
    }

    int p = g_perm[gwarp];
    size_t base = (size_t)p * KP;
    const float4* hm4 = (const float4*)(memory + (size_t)g * MEMD);

    if (valid) {
        float t_rel = (float)(t - lu);
        const float4* dm4  = (const float4*)(memory + (size_t)dst * MEMD);
        const float4* raw4 = (const float4*)raw;
        const float4* tw4  = (const float4*)time_w;
        const float4* tb4  = (const float4*)time_b;
        if (lane < 25) {
            float4 hv = hm4[lane];
            put4(base + 4 * lane, hv);              // z_src
            put4(base + 472 + 4 * lane, hv);        // h
            put4(base + 100 + 4 * lane, dm4[lane]); // z_dst
            float4 w = tw4[lane], b = tb4[lane];
            float4 tv;
            tv.x = cosf(t_rel * w.x + b.x);
            tv.y = cosf(t_rel * w.y + b.y);
            tv.z = cosf(t_rel * w.z + b.z);
            tv.w = cosf(t_rel * w.w + b.w);
            put4(base + 372 + 4 * lane, tv);        // time enc
        } else if (lane == 25) {
            zero4(base + 572);                      // K pad
        }
        for (int c4 = lane; c4 < 43; c4 += 32)
            put4(base + 200 + 4 * c4, raw4[c4]);    // raw msg
    } else {
        // invalid rows: only cols 448..575 are read by the GEMM, except rows
        // in the straddle CTA (p < round128(NV)) which need full zero-fill.
        int NV = g_cnt0;
        char* xh = (char*)g_Xhi + base * 2;
        char* xl = (char*)g_Xlo + base * 2;
        uint4 z = make_uint4(0u, 0u, 0u, 0u);
        if (p < ((NV + 127) & ~127)) {
            for (int i = lane; i < 56; i += 32) {   // cols 0..447 (16B x 56)
                ((uint4*)xh)[i] = z;
                ((uint4*)xl)[i] = z;
            }
        }
        if (lane < 3) {                             // cols 448..471
            ((uint4*)(xh + 896))[lane] = z;
            ((uint4*)(xl + 896))[lane] = z;
        }
        if (lane < 25)
            put4(base + 472 + 4 * lane, hm4[lane]); // h
        else if (lane == 25)
            zero4(base + 572);                      // K pad
    }
}

// ---------------- kernel 4: mma.sync split-bf16 GEMM + fused GRU epilogue ----
// CTA tile: 128 M x 208 N (grid.y=2). 8 warps: 4(M)x2(N), warp tile 32x104.
// 3-stage cp.async pipeline, KCHUNK=32 (18 chunks). Light CTAs start chunk 14.
#define A_ROWB 80
#define OF_AHI 0
#define OF_ALO 10240
#define OF_BHI 20480
#define OF_BLO 37120
#define STAGE  53760
#define EPI_OFF (3 * STAGE)
#define SMEM_TOT (EPI_OFF + 1024 + 128 * 53 * 4)

__device__ __forceinline__ uint32_t smem_u32(const void* p) {
    uint32_t a;
    asm("{ .reg .u64 t; cvta.to.shared.u64 t, %1; cvt.u32.u64 %0, t; }" : "=r"(a) : "l"(p));
    return a;
}
__device__ __forceinline__ void cpa16(uint32_t saddr, const void* gaddr) {
    asm volatile("cp.async.cg.shared.global [%0], [%1], 16;" :: "r"(saddr), "l"(gaddr));
}
__device__ __forceinline__ uint32_t lds32(uint32_t a) {
    uint32_t v;
    asm volatile("ld.shared.b32 %0, [%1];" : "=r"(v) : "r"(a));
    return v;
}
#define MMA(d, a0, a1, a2, a3, b0, b1)                                          \
    asm volatile("mma.sync.aligned.m16n8k16.row.col.f32.bf16.bf16.f32 "         \
                 "{%0,%1,%2,%3},{%4,%5,%6,%7},{%8,%9},{%0,%1,%2,%3};"           \
                 : "+f"(d[0]), "+f"(d[1]), "+f"(d[2]), "+f"(d[3])               \
                 : "r"(a0), "r"(a1), "r"(a2), "r"(a3), "r"(b0), "r"(b1))

__global__ __launch_bounds__(256, 1)
void k_gemm(const float* __restrict__ memory, const int* __restrict__ n_id,
            float* __restrict__ out) {
    extern __shared__ char sm[];
    const uint32_t smb = smem_u32(sm);
    const int tid = threadIdx.x;
    const int wid = tid >> 5, lane = tid & 31;
    const int g  = lane >> 2, t4 = lane & 3;
    const int wm0 = (wid & 3) * 32;
    const int wn0 = (wid >> 2) * 104;
    const size_t row0 = (size_t)blockIdx.x * 128;
    const int cy = blockIdx.y;

    const int NV = g_cnt0;
    const int c0 = (row0 >= (size_t)NV) ? 14 : 0;

    float acc[2][13][4];
#pragma unroll
    for (int mt = 0; mt < 2; mt++)
#pragma unroll
        for (int nt = 0; nt < 13; nt++)
#pragma unroll
            for (int q = 0; q < 4; q++) acc[mt][nt][q] = 0.f;

    auto load_chunk = [&](int c) {
        int kk = c * KCHUNK;
        uint32_t sb = smb + (c % 3) * STAGE;
#pragma unroll
        for (int q = tid; q < 512; q += 256) {        // A: 128 rows x 4 u4
            int r = q >> 2, u = q & 3;
            size_t gr = row0 + r;
            if (gr >= NSEL) gr = NSEL - 1;            // clamp: results discarded
            size_t go = (gr * KP + kk) * 2 + u * 16;
            uint32_t so = (uint32_t)(r * A_ROWB + u * 16);
            cpa16(sb + OF_AHI + so, (const char*)g_Xhi + go);
            cpa16(sb + OF_ALO + so, (const char*)g_Xlo + go);
        }
        for (int q = tid; q < 832; q += 256) {        // B: 208 rows x 4 u4
            int r = q >> 2, u = q & 3;
            size_t go = ((size_t)(cy * 208 + r) * KP + kk) * 2 + u * 16;
            uint32_t so = (uint32_t)(r * A_ROWB + u * 16);
            cpa16(sb + OF_BHI + so, (const char*)g_Bhi + go);
            cpa16(sb + OF_BLO + so, (const char*)g_Blo + go);
        }
        asm volatile("cp.async.commit_group;" ::: "memory");
    };

    load_chunk(c0);
    load_chunk(c0 + 1);
    for (int c = c0; c < NKCH; c++) {
        if (c + 2 < NKCH) {
            load_chunk(c + 2);
            asm volatile("cp.async.wait_group 2;" ::: "memory");
        } else if (c + 1 < NKCH) {
            asm volatile("cp.async.wait_group 1;" ::: "memory");
        } else {
            asm volatile("cp.async.wait_group 0;" ::: "memory");
        }
        __syncthreads();

        uint32_t sb = smb + (c % 3) * STAGE;
#pragma unroll
        for (int ks = 0; ks < 2; ks++) {
            const uint32_t kb2 = (uint32_t)((ks * 16 + t4 * 2) * 2);
            uint32_t ah[2][4], al[2][4];
#pragma unroll
            for (int mt = 0; mt < 2; mt++) {
                uint32_t ar = sb + (uint32_t)((wm0 + mt * 16 + g) * A_ROWB) + kb2;
                ah[mt][0] = lds32(ar + OF_AHI);
                ah[mt][1] = lds32(ar + OF_AHI + 8 * A_ROWB);
                ah[mt][2] = lds32(ar + OF_AHI + 16);
                ah[mt][3] = lds32(ar + OF_AHI + 8 * A_ROWB + 16);
                al[mt][0] = lds32(ar + OF_ALO);
                al[mt][1] = lds32(ar + OF_ALO + 8 * A_ROWB);
                al[mt][2] = lds32(ar + OF_ALO + 16);
                al[mt][3] = lds32(ar + OF_ALO + 8 * A_ROWB + 16);
            }
#pragma unroll
            for (int nt = 0; nt < 13; nt++) {
                uint32_t br = sb + (uint32_t)((wn0 + nt * 8 + g) * A_ROWB) + kb2;
                uint32_t bh0 = lds32(br + OF_BHI);
                uint32_t bh1 = lds32(br + OF_BHI + 16);
                uint32_t bl0 = lds32(br + OF_BLO);
                uint32_t bl1 = lds32(br + OF_BLO + 16);
#pragma unroll
                for (int mt = 0; mt < 2; mt++) {
                    MMA(acc[mt][nt], ah[mt][0], ah[mt][1], ah[mt][2], ah[mt][3], bh0, bh1);
                    MMA(acc[mt][nt], ah[mt][0], ah[mt][1], ah[mt][2], ah[mt][3], bl0, bl1);
                    MMA(acc[mt][nt], al[mt][0], al[mt][1], al[mt][2], al[mt][3], bh0, bh1);
                }
            }
        }
        __syncthreads();
    }

    // ---- stage orig ids / n_id / h tile (52 cols this CTA needs) ----
    int*   sOrig = (int*)(sm + EPI_OFF);
    int*   sNid  = (int*)(sm + EPI_OFF + 512);
    float* sH    = (float*)(sm + EPI_OFF + 1024);
    for (int i = tid; i < 128; i += 256) {
        size_t pr = row0 + i;
        int o = (pr < NSEL) ? g_rowmap[pr] : 0;
        sOrig[i] = o;
        sNid[i]  = n_id[o];
    }
    __syncthreads();
    for (int q = tid; q < 128 * 52; q += 256) {
        int r = q / 52, jj = q - r * 52;
        int col = cy * 52 + jj;
        float v = 0.f;
        if (row0 + r < NSEL && col < MEMD)
            v = memory[(size_t)sNid[r] * MEMD + col];
        sH[r * 53 + jj] = v;
    }
    __syncthreads();

    // ---- fused GRU epilogue ----
    const int jbase = cy * 52 + (wn0 >> 2);
#pragma unroll
    for (int mt = 0; mt < 2; mt++) {
#pragma unroll
        for (int nt = 0; nt < 13; nt++) {
            int colp = cy * 208 + wn0 + nt * 8 + t4 * 2;
            float b0 = g_bc4[colp], b1 = g_bc4[colp + 1];
            float c0v = acc[mt][nt][0] + b0, c1v = acc[mt][nt][1] + b1;
            float c2v = acc[mt][nt][2] + b0, c3v = acc[mt][nt][3] + b1;
            float d0 = __shfl_xor_sync(0xffffffffu, c0v, 1);
            float d1 = __shfl_xor_sync(0xffffffffu, c1v, 1);
            float d2 = __shfl_xor_sync(0xffffffffu, c2v, 1);
            float d3 = __shfl_xor_sync(0xffffffffu, c3v, 1);
            if (!(t4 & 1)) {                       // even t4 holds (r,z); partner (in,hn)
                int j = jbase + 2 * nt + (t4 >> 1);
                if (j < MEMD) {
                    int jj = j - cy * 52;
                    int rl = wm0 + mt * 16 + g;
                    size_t pr = row0 + rl;
                    if (pr < NSEL) {
                        float r_ = 1.f / (1.f + expf(-c0v));
                        float z_ = 1.f / (1.f + expf(-c1v));
                        float n_ = tanhf(d0 + r_ * d1);
                        out[(size_t)sOrig[rl] * MEMD + j] =
                            (1.f - z_) * n_ + z_ * sH[rl * 53 + jj];
                    }
                    if (pr + 8 < NSEL) {
                        float r_ = 1.f / (1.f + expf(-c2v));
                        float z_ = 1.f / (1.f + expf(-c3v));
                        float n_ = tanhf(d2 + r_ * d3);
                        out[(size_t)sOrig[rl + 8] * MEMD + j] =
                            (1.f - z_) * n_ + z_ * sH[(rl + 8) * 53 + jj];
                    }
                }
            }
        }
    }
}

// ---------------- launch ----------------
extern "C" void kernel_launch(void* const* d_in, const int* in_sizes, int n_in,
                              void* d_out, int out_size) {
    const float* memory      = (const float*)d_in[0];
    const int*   last_update = (const int*)  d_in[1];
    const int*   n_id        = (const int*)  d_in[2];
    const int*   loc_s       = (const int*)  d_in[3];
    const int*   dst_s       = (const int*)  d_in[4];
    const int*   t_s         = (const int*)  d_in[5];
    const float* raw_msg_s   = (const float*)d_in[6];
    const int*   loc_d       = (const int*)  d_in[7];
    const int*   dst_d       = (const int*)  d_in[8];
    const int*   t_d         = (const int*)  d_in[9];
    const float* raw_msg_d   = (const float*)d_in[10];
    const float* time_w      = (const float*)d_in[11];
    const float* time_b      = (const float*)d_in[12];
    const float* W_ih        = (const float*)d_in[13];
    const float* W_hh        = (const float*)d_in[14];
    const float* b_ih        = (const float*)d_in[15];
    const float* b_hh        = (const float*)d_in[16];

    float* out_mem = (float*)d_out;
    float* out_lu  = (out_size >= NSEL * MEMD + NSEL) ? out_mem + (size_t)NSEL * MEMD
                                                      : nullptr;

    cudaFuncSetAttribute(k_gemm, cudaFuncAttributeMaxDynamicSharedMemorySize, SMEM_TOT);

    k_init<<<(NSEL + 255) / 256, 256>>>();
    k_aggr<<<(2 * NE + 255) / 256, 256>>>(loc_s, t_s, loc_d, t_d);
    k_part<<<(NSEL + 255) / 256, 256>>>();
    k_prep<<<(NCP * KP + 255) / 256, 256>>>(W_ih, W_hh, b_ih, b_hh);
    k_build<<<NSEL / 8, 256>>>(memory, last_update, n_id,
                               dst_s, t_s, raw_msg_s,
                               dst_d, t_d, raw_msg_d,
                               time_w, time_b, out_lu);
    k_gemm<<<dim3((NSEL + 127) / 128, 2), 256, SMEM_TOT>>>(memory, n_id, out_mem);
}

// round 14
// speedup vs baseline: 2.9299x; 1.1575x over previous
#include <cuda_runtime.h>
#include <cuda_bf16.h>
#include <math.h>
#include <cstdint>

#define NSEL  200000
#define NE    100000
#define MEMD  100
#define RAWD  172
#define KREAL 572           // 472 msg + 100 h
#define KP    576           // padded K (18 chunks of 32)
#define NCP   416           // blocked cols: rz[0,208) in[208,312) hn[312,416)
#define KCHUNK 32
#define NKCH   18

// ---- scratch (static __device__, allocation-free) ----
__device__ unsigned long long g_key[NSEL];
__device__ __nv_bfloat16 g_Xhi[(size_t)NSEL * KP];
__device__ __nv_bfloat16 g_Xlo[(size_t)NSEL * KP];
__device__ __nv_bfloat16 g_Bhi[(size_t)NCP * KP];
__device__ __nv_bfloat16 g_Blo[(size_t)NCP * KP];
__device__ float g_bcn[NCP];                        // blocked-layout biases
__device__ int g_cnt0, g_cnt1;
__device__ int g_perm[NSEL];                        // orig node -> compacted row
__device__ int g_rowmap[NSEL];                      // compacted row -> orig node

// ---------------- kernel 0: init ----------------
__global__ void k_init() {
    int i = blockIdx.x * blockDim.x + threadIdx.x;
    if (i < NSEL) g_key[i] = 0ULL;
    if (i == 0) { g_cnt0 = 0; g_cnt1 = 0; }
}

// ---------------- kernel 1: last aggregation ----------------
__global__ void k_aggr(const int* __restrict__ loc_s, const int* __restrict__ t_s,
                       const int* __restrict__ loc_d, const int* __restrict__ t_d) {
    int i = blockIdx.x * blockDim.x + threadIdx.x;
    if (i >= 2 * NE) return;
    int loc, t;
    if (i < NE) { loc = loc_s[i]; t = t_s[i]; }
    else        { loc = loc_d[i - NE]; t = t_d[i - NE]; }
    unsigned long long key =
        ((unsigned long long)(unsigned int)(t + 1) << 32) | (unsigned int)i;
    atomicMax(&g_key[loc], key);
}

// ---------------- kernel 1b: partition rows ----------------
__global__ void k_part() {
    int i = blockIdx.x * blockDim.x + threadIdx.x;
    if (i >= NSEL) return;
    int lane = threadIdx.x & 31;
    bool valid = (g_key[i] != 0ULL);
    unsigned mv = __ballot_sync(0xffffffffu, valid);
    int nv = __popc(mv), ni = 32 - nv;
    int bv = 0, bi = 0;
    if (lane == 0) {
        if (nv) bv = atomicAdd(&g_cnt0, nv);
        if (ni) bi = atomicAdd(&g_cnt1, ni);
    }
    bv = __shfl_sync(0xffffffffu, bv, 0);
    bi = __shfl_sync(0xffffffffu, bi, 0);
    unsigned lt = (1u << lane) - 1u;
    int p = valid ? (bv + __popc(mv & lt))
                  : (NSEL - 1 - (bi + __popc(~mv & lt)));
    g_perm[i] = p;
    g_rowmap[p] = i;
}

// ---------------- kernel 2: weight prep (gate-blocked, bf16 hi/lo) -----------
// cols [0,200): r0 z0 r1 z1 ... (dense over K)
// cols [208,308): in_j  (W_ih rows 200+j, zero for k>=472)
// cols [312,412): hn_j  (W_hh rows 200+j, zero for k<472)
__global__ void k_prep(const float* __restrict__ W_ih, const float* __restrict__ W_hh,
                       const float* __restrict__ b_ih, const float* __restrict__ b_hh) {
    int idx = blockIdx.x * blockDim.x + threadIdx.x;
    if (idx < NCP * KP) {
        int col = idx / KP;
        int k   = idx % KP;
        float v = 0.f;
        if (k < KREAL) {
            if (col < 200) {
                int j = col >> 1;
                int rw = (col & 1) ? 100 + j : j;
                v = (k < 472) ? W_ih[(size_t)rw * 472 + k]
                              : W_hh[(size_t)rw * 100 + (k - 472)];
            } else if (col >= 208 && col < 308) {
                int j = col - 208;
                if (k < 472) v = W_ih[(size_t)(200 + j) * 472 + k];
            } else if (col >= 312 && col < 412) {
                int j = col - 312;
                if (k >= 472) v = W_hh[(size_t)(200 + j) * 100 + (k - 472)];
            }
        }
        __nv_bfloat16 h = __float2bfloat16(v);
        g_Bhi[idx] = h;
        g_Blo[idx] = __float2bfloat16(v - __bfloat162float(h));
    }
    if (idx < NCP) {
        float b = 0.f;
        if (idx < 200) {
            int j = idx >> 1;
            b = (idx & 1) ? (b_ih[100 + j] + b_hh[100 + j]) : (b_ih[j] + b_hh[j]);
        } else if (idx >= 208 && idx < 308) {
            b = b_ih[200 + (idx - 208)];
        } else if (idx >= 312 && idx < 412) {
            b = b_hh[200 + (idx - 312)];
        }
        g_bcn[idx] = b;
    }
}

// ---------------- kernel 3: build X rows (compacted, vectorized) -------------
__device__ __forceinline__ void put4(size_t idx, float4 v) {
    __nv_bfloat162 h01 = __floats2bfloat162_rn(v.x, v.y);
    __nv_bfloat162 h23 = __floats2bfloat162_rn(v.z, v.w);
    __nv_bfloat162 l01 = __floats2bfloat162_rn(v.x - __low2float(h01),
                                               v.y - __high2float(h01));
    __nv_bfloat162 l23 = __floats2bfloat162_rn(v.z - __low2float(h23),
                                               v.w - __high2float(h23));
    uint2 uh, ul;
    uh.x = *reinterpret_cast<uint32_t*>(&h01);
    uh.y = *reinterpret_cast<uint32_t*>(&h23);
    ul.x = *reinterpret_cast<uint32_t*>(&l01);
    ul.y = *reinterpret_cast<uint32_t*>(&l23);
    *reinterpret_cast<uint2*>(g_Xhi + idx) = uh;
    *reinterpret_cast<uint2*>(g_Xlo + idx) = ul;
}
__device__ __forceinline__ void zero4(size_t idx) {
    uint2 z = make_uint2(0u, 0u);
    *reinterpret_cast<uint2*>(g_Xhi + idx) = z;
    *reinterpret_cast<uint2*>(g_Xlo + idx) = z;
}

__global__ void k_build(const float* __restrict__ memory, const int* __restrict__ last_update,
                        const int* __restrict__ n_id,
                        const int* __restrict__ dst_s, const int* __restrict__ t_s,
                        const float* __restrict__ raw_s,
                        const int* __restrict__ dst_d, const int* __restrict__ t_d,
                        const float* __restrict__ raw_d,
                        const float* __restrict__ time_w, const float* __restrict__ time_b,
                        float* __restrict__ out_lu) {
    int gwarp = (blockIdx.x * blockDim.x + threadIdx.x) >> 5;
    int lane  = threadIdx.x & 31;
    if (gwarp >= NSEL) return;

    int g = n_id[gwarp];
    unsigned long long key = g_key[gwarp];
    int lu = last_update[g];
    bool valid = (key != 0ULL);

    int dst = 0, t = 0;
    const float* raw = raw_s;
    if (valid) {
        unsigned int e = (unsigned int)key;
        t = (int)(key >> 32) - 1;
        if (e < NE) { dst = dst_s[e]; raw = raw_s + (size_t)e * RAWD; }
        else        { unsigned int e2 = e - NE; dst = dst_d[e2]; raw = raw_d + (size_t)e2 * RAWD; }
    }
    if (out_lu && lane == 0) {
        int nl = valid ? max(lu, t) : lu;
        out_lu[gwarp] = (float)nl;
    }

    int p = g_perm[gwarp];
    size_t base = (size_t)p * KP;
    const float4* hm4 = (const float4*)(memory + (size_t)g * MEMD);

    if (valid) {
        float t_rel = (float)(t - lu);
        const float4* dm4  = (const float4*)(memory + (size_t)dst * MEMD);
        const float4* raw4 = (const float4*)raw;
        const float4* tw4  = (const float4*)time_w;
        const float4* tb4  = (const float4*)time_b;
        if (lane < 25) {
            float4 hv = hm4[lane];
            put4(base + 4 * lane, hv);              // z_src
            put4(base + 472 + 4 * lane, hv);        // h
            put4(base + 100 + 4 * lane, dm4[lane]); // z_dst
            float4 w = tw4[lane], b = tb4[lane];
            float4 tv;
            tv.x = cosf(t_rel * w.x + b.x);
            tv.y = cosf(t_rel * w.y + b.y);
            tv.z = cosf(t_rel * w.z + b.z);
            tv.w = cosf(t_rel * w.w + b.w);
            put4(base + 372 + 4 * lane, tv);        // time enc
        } else if (lane == 25) {
            zero4(base + 572);                      // K pad
        }
        for (int c4 = lane; c4 < 43; c4 += 32)
            put4(base + 200 + 4 * c4, raw4[c4]);    // raw msg
    } else {
        int NV = g_cnt0;
        char* xh = (char*)g_Xhi + base * 2;
        char* xl = (char*)g_Xlo + base * 2;
        uint4 z = make_uint4(0u, 0u, 0u, 0u);
        if (p < ((NV + 127) & ~127)) {
            for (int i = lane; i < 56; i += 32) {   // cols 0..447
                ((uint4*)xh)[i] = z;
                ((uint4*)xl)[i] = z;
            }
        }
        if (lane < 3) {                             // cols 448..471
            ((uint4*)(xh + 896))[lane] = z;
            ((uint4*)(xl + 896))[lane] = z;
        }
        if (lane < 25)
            put4(base + 472 + 4 * lane, hm4[lane]); // h
        else if (lane == 25)
            zero4(base + 572);
    }
}

// ---------------- kernel 4: gate-blocked split-bf16 GEMM + smem GRU epilogue -
// CTA: 64 M x 416 N. 8 warps: 2(M) x 4(N, frag-interleaved f = nw + 4*nt).
// Frag activity: f<26 (rz): all chunks; f<39 (in): c<=14; else (hn): c>=14.
// Light CTAs (row0>=NV) run chunks 14..17 only.
#define A_ROWB 80
#define OF_AHI 0
#define OF_ALO 5120
#define OF_BHI 10240
#define OF_BLO 43520
#define STAGE  76800
#define SMEM_TOT (2 * STAGE)
#define PST 420
#define IDS_OFF 110592

__device__ __forceinline__ uint32_t smem_u32(const void* p) {
    uint32_t a;
    asm("{ .reg .u64 t; cvta.to.shared.u64 t, %1; cvt.u32.u64 %0, t; }" : "=r"(a) : "l"(p));
    return a;
}
__device__ __forceinline__ void cpa16(uint32_t saddr, const void* gaddr) {
    asm volatile("cp.async.cg.shared.global [%0], [%1], 16;" :: "r"(saddr), "l"(gaddr));
}
__device__ __forceinline__ uint32_t lds32(uint32_t a) {
    uint32_t v;
    asm volatile("ld.shared.b32 %0, [%1];" : "=r"(v) : "r"(a));
    return v;
}
#define MMA(d, a0, a1, a2, a3, b0, b1)                                          \
    asm volatile("mma.sync.aligned.m16n8k16.row.col.f32.bf16.bf16.f32 "         \
                 "{%0,%1,%2,%3},{%4,%5,%6,%7},{%8,%9},{%0,%1,%2,%3};"           \
                 : "+f"(d[0]), "+f"(d[1]), "+f"(d[2]), "+f"(d[3])               \
                 : "r"(a0), "r"(a1), "r"(a2), "r"(a3), "r"(b0), "r"(b1))

__global__ __launch_bounds__(256, 1)
void k_gemm(const float* __restrict__ memory, const int* __restrict__ n_id,
            float* __restrict__ out) {
    extern __shared__ char sm[];
    const uint32_t smb = smem_u32(sm);
    const int tid = threadIdx.x;
    const int wid = tid >> 5, lane = tid & 31;
    const int g  = lane >> 2, t4 = lane & 3;
    const int mw = wid >> 2;            // 0..1
    const int nw = wid & 3;             // 0..3
    const int wm0 = mw * 32;
    const size_t row0 = (size_t)blockIdx.x * 64;

    const int NV = g_cnt0;
    const int c0 = (row0 >= (size_t)NV) ? 14 : 0;

    float acc[2][13][4];
#pragma unroll
    for (int mt = 0; mt < 2; mt++)
#pragma unroll
        for (int nt = 0; nt < 13; nt++)
#pragma unroll
            for (int q = 0; q < 4; q++) acc[mt][nt][q] = 0.f;

    auto load_chunk = [&](int c) {
        int kk = c * KCHUNK;
        uint32_t sb = smb + (c & 1) * STAGE;
        {   // A: 64 rows x 4 u4  (exactly 1 iter/thread)
            int r = tid >> 2, u = tid & 3;
            size_t gr = row0 + r;
            if (gr >= NSEL) gr = NSEL - 1;
            size_t go = (gr * KP + kk) * 2 + u * 16;
            uint32_t so = (uint32_t)(r * A_ROWB + u * 16);
            cpa16(sb + OF_AHI + so, (const char*)g_Xhi + go);
            cpa16(sb + OF_ALO + so, (const char*)g_Xlo + go);
        }
        for (int q = tid; q < 1664; q += 256) {   // B: 416 rows x 4 u4 (predicated)
            int r = q >> 2, u = q & 3;
            bool need = (r < 208) || ((r < 312) ? (c <= 14) : (c >= 14));
            if (need) {
                size_t go = ((size_t)r * KP + kk) * 2 + u * 16;
                uint32_t so = (uint32_t)(r * A_ROWB + u * 16);
                cpa16(sb + OF_BHI + so, (const char*)g_Bhi + go);
                cpa16(sb + OF_BLO + so, (const char*)g_Blo + go);
            }
        }
        asm volatile("cp.async.commit_group;" ::: "memory");
    };

    load_chunk(c0);
    for (int c = c0; c < NKCH; c++) {
        if (c + 1 < NKCH) {
            load_chunk(c + 1);
            asm volatile("cp.async.wait_group 1;" ::: "memory");
        } else {
            asm volatile("cp.async.wait_group 0;" ::: "memory");
        }
        __syncthreads();

        uint32_t sb = smb + (c & 1) * STAGE;
#pragma unroll
        for (int ks = 0; ks < 2; ks++) {
            const uint32_t kb2 = (uint32_t)((ks * 16 + t4 * 2) * 2);
            uint32_t ah[2][4], al[2][4];
#pragma unroll
            for (int mt = 0; mt < 2; mt++) {
                uint32_t ar = sb + (uint32_t)((wm0 + mt * 16 + g) * A_ROWB) + kb2;
                ah[mt][0] = lds32(ar + OF_AHI);
                ah[mt][1] = lds32(ar + OF_AHI + 8 * A_ROWB);
                ah[mt][2] = lds32(ar + OF_AHI + 16);
                ah[mt][3] = lds32(ar + OF_AHI + 8 * A_ROWB + 16);
                al[mt][0] = lds32(ar + OF_ALO);
                al[mt][1] = lds32(ar + OF_ALO + 8 * A_ROWB);
                al[mt][2] = lds32(ar + OF_ALO + 16);
                al[mt][3] = lds32(ar + OF_ALO + 8 * A_ROWB + 16);
            }
#pragma unroll
            for (int nt = 0; nt < 13; nt++) {
                int fr = nw + 4 * nt;
                bool act = (fr < 26) || ((fr < 39) ? (c <= 14) : (c >= 14));
                if (act) {
                    uint32_t br = sb + (uint32_t)((8 * fr + g) * A_ROWB) + kb2;
                    uint32_t bh0 = lds32(br + OF_BHI);
                    uint32_t bh1 = lds32(br + OF_BHI + 16);
                    uint32_t bl0 = lds32(br + OF_BLO);
                    uint32_t bl1 = lds32(br + OF_BLO + 16);
#pragma unroll
                    for (int mt = 0; mt < 2; mt++) {
                        MMA(acc[mt][nt], ah[mt][0], ah[mt][1], ah[mt][2], ah[mt][3], bh0, bh1);
                        MMA(acc[mt][nt], ah[mt][0], ah[mt][1], ah[mt][2], ah[mt][3], bl0, bl1);
                        MMA(acc[mt][nt], al[mt][0], al[mt][1], al[mt][2], al[mt][3], bh0, bh1);
                    }
                }
            }
        }
        __syncthreads();
    }

    // ---- dump pre-activations to smem (overlay stage buffers) ----
    float* Ps = (float*)sm;
    int* sOrig = (int*)(sm + IDS_OFF);
    int* sNid  = sOrig + 64;
#pragma unroll
    for (int mt = 0; mt < 2; mt++) {
#pragma unroll
        for (int nt = 0; nt < 13; nt++) {
            int col = 8 * (nw + 4 * nt) + 2 * t4;
            int r1 = wm0 + mt * 16 + g;
            *(float2*)&Ps[r1 * PST + col] = make_float2(acc[mt][nt][0], acc[mt][nt][1]);
            *(float2*)&Ps[(r1 + 8) * PST + col] = make_float2(acc[mt][nt][2], acc[mt][nt][3]);
        }
    }
    if (tid < 64) {
        size_t pr = row0 + tid;
        int o = (pr < NSEL) ? g_rowmap[pr] : 0;
        sOrig[tid] = o;
        sNid[tid]  = n_id[o];
    }
    __syncthreads();

    // ---- GRU combine: 64 rows x 100 j ----
    for (int q = tid; q < 64 * MEMD; q += 256) {
        int r = q / MEMD;
        int j = q - r * MEMD;
        if (row0 + r >= NSEL) break;
        const float* P = Ps + r * PST;
        float pr = P[2 * j]       + g_bcn[2 * j];
        float pz = P[2 * j + 1]   + g_bcn[2 * j + 1];
        float pi = P[208 + j]     + g_bcn[208 + j];
        float ph = P[312 + j]     + g_bcn[312 + j];
        float rr = 1.f / (1.f + expf(-pr));
        float zz = 1.f / (1.f + expf(-pz));
        float nn = tanhf(pi + rr * ph);
        float h  = memory[(size_t)sNid[r] * MEMD + j];
        out[(size_t)sOrig[r] * MEMD + j] = (1.f - zz) * nn + zz * h;
    }
}

// ---------------- launch ----------------
extern "C" void kernel_launch(void* const* d_in, const int* in_sizes, int n_in,
                              void* d_out, int out_size) {
    const float* memory      = (const float*)d_in[0];
    const int*   last_update = (const int*)  d_in[1];
    const int*   n_id        = (const int*)  d_in[2];
    const int*   loc_s       = (const int*)  d_in[3];
    const int*   dst_s       = (const int*)  d_in[4];
    const int*   t_s         = (const int*)  d_in[5];
    const float* raw_msg_s   = (const float*)d_in[6];
    const int*   loc_d       = (const int*)  d_in[7];
    const int*   dst_d       = (const int*)  d_in[8];
    const int*   t_d         = (const int*)  d_in[9];
    const float* raw_msg_d   = (const float*)d_in[10];
    const float* time_w      = (const float*)d_in[11];
    const float* time_b      = (const float*)d_in[12];
    const float* W_ih        = (const float*)d_in[13];
    const float* W_hh        = (const float*)d_in[14];
    const float* b_ih        = (const float*)d_in[15];
    const float* b_hh        = (const float*)d_in[16];

    float* out_mem = (float*)d_out;
    float* out_lu  = (out_size >= NSEL * MEMD + NSEL) ? out_mem + (size_t)NSEL * MEMD
                                                      : nullptr;

    cudaFuncSetAttribute(k_gemm, cudaFuncAttributeMaxDynamicSharedMemorySize, SMEM_TOT);

    k_init<<<(NSEL + 255) / 256, 256>>>();
    k_aggr<<<(2 * NE + 255) / 256, 256>>>(loc_s, t_s, loc_d, t_d);
    k_part<<<(NSEL + 255) / 256, 256>>>();
    k_prep<<<(NCP * KP + 255) / 256, 256>>>(W_ih, W_hh, b_ih, b_hh);
    k_build<<<NSEL / 8, 256>>>(memory, last_update, n_id,
                               dst_s, t_s, raw_msg_s,
                               dst_d, t_d, raw_msg_d,
                               time_w, time_b, out_lu);
    k_gemm<<<(NSEL + 63) / 64, 256, SMEM_TOT>>>(memory, n_id, out_mem);
}

// round 15
// speedup vs baseline: 3.5317x; 1.2054x over previous
#include <cuda_runtime.h>
#include <cuda_fp16.h>
#include <math.h>
#include <cstdint>

#define NSEL  200000
#define NE    100000
#define MEMD  100
#define RAWD  172
#define KREAL 572           // 472 msg + 100 h
#define KP    576           // padded K (18 chunks of 32)
#define NCP   416           // blocked cols: rz[0,208) in[208,312) hn[312,416)
#define KCHUNK 32
#define NKCH   18

// ---- scratch (static __device__, allocation-free) ----
__device__ unsigned long long g_key[NSEL];
__device__ __half g_Xhi[(size_t)NSEL * KP];
__device__ __half g_Xlo[(size_t)NSEL * KP];
__device__ __half g_Bh[(size_t)NCP * KP];           // single fp16 weight plane
__device__ float g_bcn[NCP];                        // blocked-layout biases
__device__ int g_cnt0, g_cnt1;
__device__ int g_perm[NSEL];                        // orig node -> compacted row
__device__ int g_rowmap[NSEL];                      // compacted row -> orig node

// ---------------- kernel 0: init ----------------
__global__ void k_init() {
    int i = blockIdx.x * blockDim.x + threadIdx.x;
    if (i < NSEL) g_key[i] = 0ULL;
    if (i == 0) { g_cnt0 = 0; g_cnt1 = 0; }
}

// ---------------- kernel 1: last aggregation ----------------
__global__ void k_aggr(const int* __restrict__ loc_s, const int* __restrict__ t_s,
                       const int* __restrict__ loc_d, const int* __restrict__ t_d) {
    int i = blockIdx.x * blockDim.x + threadIdx.x;
    if (i >= 2 * NE) return;
    int loc, t;
    if (i < NE) { loc = loc_s[i]; t = t_s[i]; }
    else        { loc = loc_d[i - NE]; t = t_d[i - NE]; }
    unsigned long long key =
        ((unsigned long long)(unsigned int)(t + 1) << 32) | (unsigned int)i;
    atomicMax(&g_key[loc], key);
}

// ---------------- kernel 1b: partition rows ----------------
__global__ void k_part() {
    int i = blockIdx.x * blockDim.x + threadIdx.x;
    if (i >= NSEL) return;
    int lane = threadIdx.x & 31;
    bool valid = (g_key[i] != 0ULL);
    unsigned mv = __ballot_sync(0xffffffffu, valid);
    int nv = __popc(mv), ni = 32 - nv;
    int bv = 0, bi = 0;
    if (lane == 0) {
        if (nv) bv = atomicAdd(&g_cnt0, nv);
        if (ni) bi = atomicAdd(&g_cnt1, ni);
    }
    bv = __shfl_sync(0xffffffffu, bv, 0);
    bi = __shfl_sync(0xffffffffu, bi, 0);
    unsigned lt = (1u << lane) - 1u;
    int p = valid ? (bv + __popc(mv & lt))
                  : (NSEL - 1 - (bi + __popc(~mv & lt)));
    g_perm[i] = p;
    g_rowmap[p] = i;
}

// ---------------- kernel 2: weight prep (gate-blocked, single fp16) ----------
// cols [0,200): r0 z0 r1 z1 ... (dense over K)
// cols [208,308): in_j  (W_ih rows 200+j, zero for k>=472)
// cols [312,412): hn_j  (W_hh rows 200+j, zero for k<472)
__global__ void k_prep(const float* __restrict__ W_ih, const float* __restrict__ W_hh,
                       const float* __restrict__ b_ih, const float* __restrict__ b_hh) {
    int idx = blockIdx.x * blockDim.x + threadIdx.x;
    if (idx < NCP * KP) {
        int col = idx / KP;
        int k   = idx % KP;
        float v = 0.f;
        if (k < KREAL) {
            if (col < 200) {
                int j = col >> 1;
                int rw = (col & 1) ? 100 + j : j;
                v = (k < 472) ? W_ih[(size_t)rw * 472 + k]
                              : W_hh[(size_t)rw * 100 + (k - 472)];
            } else if (col >= 208 && col < 308) {
                int j = col - 208;
                if (k < 472) v = W_ih[(size_t)(200 + j) * 472 + k];
            } else if (col >= 312 && col < 412) {
                int j = col - 312;
                if (k >= 472) v = W_hh[(size_t)(200 + j) * 100 + (k - 472)];
            }
        }
        g_Bh[idx] = __float2half_rn(v);
    }
    if (idx < NCP) {
        float b = 0.f;
        if (idx < 200) {
            int j = idx >> 1;
            b = (idx & 1) ? (b_ih[100 + j] + b_hh[100 + j]) : (b_ih[j] + b_hh[j]);
        } else if (idx >= 208 && idx < 308) {
            b = b_ih[200 + (idx - 208)];
        } else if (idx >= 312 && idx < 412) {
            b = b_hh[200 + (idx - 312)];
        }
        g_bcn[idx] = b;
    }
}

// ---------------- kernel 3: build X rows (compacted, fp16 hi/lo) -------------
__device__ __forceinline__ void put4(size_t idx, float4 v) {
    __half hx = __float2half_rn(v.x), hy = __float2half_rn(v.y);
    __half hz = __float2half_rn(v.z), hw = __float2half_rn(v.w);
    __half lx = __float2half_rn(v.x - __half2float(hx));
    __half ly = __float2half_rn(v.y - __half2float(hy));
    __half lz = __float2half_rn(v.z - __half2float(hz));
    __half lw = __float2half_rn(v.w - __half2float(hw));
    __half2 h01 = __halves2half2(hx, hy), h23 = __halves2half2(hz, hw);
    __half2 l01 = __halves2half2(lx, ly), l23 = __halves2half2(lz, lw);
    uint2 uh, ul;
    uh.x = *reinterpret_cast<uint32_t*>(&h01);
    uh.y = *reinterpret_cast<uint32_t*>(&h23);
    ul.x = *reinterpret_cast<uint32_t*>(&l01);
    ul.y = *reinterpret_cast<uint32_t*>(&l23);
    *reinterpret_cast<uint2*>(g_Xhi + idx) = uh;
    *reinterpret_cast<uint2*>(g_Xlo + idx) = ul;
}
__device__ __forceinline__ void zero4(size_t idx) {
    uint2 z = make_uint2(0u, 0u);
    *reinterpret_cast<uint2*>(g_Xhi + idx) = z;
    *reinterpret_cast<uint2*>(g_Xlo + idx) = z;
}

__global__ void k_build(const float* __restrict__ memory, const int* __restrict__ last_update,
                        const int* __restrict__ n_id,
                        const int* __restrict__ dst_s, const int* __restrict__ t_s,
                        const float* __restrict__ raw_s,
                        const int* __restrict__ dst_d, const int* __restrict__ t_d,
                        const float* __restrict__ raw_d,
                        const float* __restrict__ time_w, const float* __restrict__ time_b,
                        float* __restrict__ out_lu) {
    int gwarp = (blockIdx.x * blockDim.x + threadIdx.x) >> 5;
    int lane  = threadIdx.x & 31;
    if (gwarp >= NSEL) return;

    int g = n_id[gwarp];
    unsigned long long key = g_key[gwarp];
    int lu = last_update[g];
    bool valid = (key != 0ULL);

    int dst = 0, t = 0;
    const float* raw = raw_s;
    if (valid) {
        unsigned int e = (unsigned int)key;
        t = (int)(key >> 32) - 1;
        if (e < NE) { dst = dst_s[e]; raw = raw_s + (size_t)e * RAWD; }
        else        { unsigned int e2 = e - NE; dst = dst_d[e2]; raw = raw_d + (size_t)e2 * RAWD; }
    }
    if (out_lu && lane == 0) {
        int nl = valid ? max(lu, t) : lu;
        out_lu[gwarp] = (float)nl;
    }

    int p = g_perm[gwarp];
    size_t base = (size_t)p * KP;
    const float4* hm4 = (const float4*)(memory + (size_t)g * MEMD);

    if (valid) {
        float t_rel = (float)(t - lu);
        const float4* dm4  = (const float4*)(memory + (size_t)dst * MEMD);
        const float4* raw4 = (const float4*)raw;
        const float4* tw4  = (const float4*)time_w;
        const float4* tb4  = (const float4*)time_b;
        if (lane < 25) {
            float4 hv = hm4[lane];
            put4(base + 4 * lane, hv);              // z_src
            put4(base + 472 + 4 * lane, hv);        // h
            put4(base + 100 + 4 * lane, dm4[lane]); // z_dst
            float4 w = tw4[lane], b = tb4[lane];
            float4 tv;
            tv.x = cosf(t_rel * w.x + b.x);
            tv.y = cosf(t_rel * w.y + b.y);
            tv.z = cosf(t_rel * w.z + b.z);
            tv.w = cosf(t_rel * w.w + b.w);
            put4(base + 372 + 4 * lane, tv);        // time enc
        } else if (lane == 25) {
            zero4(base + 572);                      // K pad
        }
        for (int c4 = lane; c4 < 43; c4 += 32)
            put4(base + 200 + 4 * c4, raw4[c4]);    // raw msg
    } else {
        int NV = g_cnt0;
        char* xh = (char*)g_Xhi + base * 2;
        char* xl = (char*)g_Xlo + base * 2;
        uint4 z = make_uint4(0u, 0u, 0u, 0u);
        if (p < ((NV + 127) & ~127)) {
            for (int i = lane; i < 56; i += 32) {   // cols 0..447
                ((uint4*)xh)[i] = z;
                ((uint4*)xl)[i] = z;
            }
        }
        if (lane < 3) {                             // cols 448..471
            ((uint4*)(xh + 896))[lane] = z;
            ((uint4*)(xl + 896))[lane] = z;
        }
        if (lane < 25)
            put4(base + 472 + 4 * lane, hm4[lane]); // h
        else if (lane == 25)
            zero4(base + 572);
    }
}

// ---------------- kernel 4: gate-blocked 2-product fp16 GEMM + GRU epilogue --
// CTA: 64 M x 416 N. 8 warps: 2(M) x 4(N, frag-interleaved f = nw + 4*nt).
// D = Ahi@B + Alo@B  (A hi/lo fp16, B single fp16, fp32 accum)
// Frag activity: f<26 (rz): all chunks; f<39 (in): c<=14; else (hn): c>=14.
// Light CTAs (row0>=NV) run chunks 14..17 only.
#define A_ROWB 80
#define OF_AHI 0
#define OF_ALO 5120
#define OF_BH  10240
#define STAGE  43520
#define SMEM_TOT (64 * 420 * 4 + 768)
#define PST 420
#define IDS_OFF (64 * 420 * 4)

__device__ __forceinline__ uint32_t smem_u32(const void* p) {
    uint32_t a;
    asm("{ .reg .u64 t; cvta.to.shared.u64 t, %1; cvt.u32.u64 %0, t; }" : "=r"(a) : "l"(p));
    return a;
}
__device__ __forceinline__ void cpa16(uint32_t saddr, const void* gaddr) {
    asm volatile("cp.async.cg.shared.global [%0], [%1], 16;" :: "r"(saddr), "l"(gaddr));
}
__device__ __forceinline__ uint32_t lds32(uint32_t a) {
    uint32_t v;
    asm volatile("ld.shared.b32 %0, [%1];" : "=r"(v) : "r"(a));
    return v;
}
#define MMA(d, a0, a1, a2, a3, b0, b1)                                          \
    asm volatile("mma.sync.aligned.m16n8k16.row.col.f32.f16.f16.f32 "           \
                 "{%0,%1,%2,%3},{%4,%5,%6,%7},{%8,%9},{%0,%1,%2,%3};"           \
                 : "+f"(d[0]), "+f"(d[1]), "+f"(d[2]), "+f"(d[3])               \
                 : "r"(a0), "r"(a1), "r"(a2), "r"(a3), "r"(b0), "r"(b1))

__global__ __launch_bounds__(256, 1)
void k_gemm(const float* __restrict__ memory, const int* __restrict__ n_id,
            float* __restrict__ out) {
    extern __shared__ char sm[];
    const uint32_t smb = smem_u32(sm);
    const int tid = threadIdx.x;
    const int wid = tid >> 5, lane = tid & 31;
    const int g  = lane >> 2, t4 = lane & 3;
    const int mw = wid >> 2;            // 0..1
    const int nw = wid & 3;             // 0..3
    const int wm0 = mw * 32;
    const size_t row0 = (size_t)blockIdx.x * 64;

    const int NV = g_cnt0;
    const int c0 = (row0 >= (size_t)NV) ? 14 : 0;

    float acc[2][13][4];
#pragma unroll
    for (int mt = 0; mt < 2; mt++)
#pragma unroll
        for (int nt = 0; nt < 13; nt++)
#pragma unroll
            for (int q = 0; q < 4; q++) acc[mt][nt][q] = 0.f;

    auto load_chunk = [&](int c) {
        int kk = c * KCHUNK;
        uint32_t sb = smb + (c & 1) * STAGE;
        {   // A: 64 rows x 4 u4  (exactly 1 iter/thread)
            int r = tid >> 2, u = tid & 3;
            size_t gr = row0 + r;
            if (gr >= NSEL) gr = NSEL - 1;
            size_t go = (gr * KP + kk) * 2 + u * 16;
            uint32_t so = (uint32_t)(r * A_ROWB + u * 16);
            cpa16(sb + OF_AHI + so, (const char*)g_Xhi + go);
            cpa16(sb + OF_ALO + so, (const char*)g_Xlo + go);
        }
        for (int q = tid; q < 1664; q += 256) {   // B: 416 rows x 4 u4 (predicated)
            int r = q >> 2, u = q & 3;
            bool need = (r < 208) || ((r < 312) ? (c <= 14) : (c >= 14));
            if (need) {
                size_t go = ((size_t)r * KP + kk) * 2 + u * 16;
                uint32_t so = (uint32_t)(r * A_ROWB + u * 16);
                cpa16(sb + OF_BH + so, (const char*)g_Bh + go);
            }
        }
        asm volatile("cp.async.commit_group;" ::: "memory");
    };

    load_chunk(c0);
    for (int c = c0; c < NKCH; c++) {
        if (c + 1 < NKCH) {
            load_chunk(c + 1);
            asm volatile("cp.async.wait_group 1;" ::: "memory");
        } else {
            asm volatile("cp.async.wait_group 0;" ::: "memory");
        }
        __syncthreads();

        uint32_t sb = smb + (c & 1) * STAGE;
#pragma unroll
        for (int ks = 0; ks < 2; ks++) {
            const uint32_t kb2 = (uint32_t)((ks * 16 + t4 * 2) * 2);
            uint32_t ah[2][4], al[2][4];
#pragma unroll
            for (int mt = 0; mt < 2; mt++) {
                uint32_t ar = sb + (uint32_t)((wm0 + mt * 16 + g) * A_ROWB) + kb2;
                ah[mt][0] = lds32(ar + OF_AHI);
                ah[mt][1] = lds32(ar + OF_AHI + 8 * A_ROWB);
                ah[mt][2] = lds32(ar + OF_AHI + 16);
                ah[mt][3] = lds32(ar + OF_AHI + 8 * A_ROWB + 16);
                al[mt][0] = lds32(ar + OF_ALO);
                al[mt][1] = lds32(ar + OF_ALO + 8 * A_ROWB);
                al[mt][2] = lds32(ar + OF_ALO + 16);
                al[mt][3] = lds32(ar + OF_ALO + 8 * A_ROWB + 16);
            }
#pragma unroll
            for (int nt = 0; nt < 13; nt++) {
                int fr = nw + 4 * nt;
                bool act = (fr < 26) || ((fr < 39) ? (c <= 14) : (c >= 14));
                if (act) {
                    uint32_t br = sb + (uint32_t)((8 * fr + g) * A_ROWB) + kb2;
                    uint32_t b0 = lds32(br + OF_BH);
                    uint32_t b1 = lds32(br + OF_BH + 16);
#pragma unroll
                    for (int mt = 0; mt < 2; mt++) {
                        MMA(acc[mt][nt], ah[mt][0], ah[mt][1], ah[mt][2], ah[mt][3], b0, b1);
                        MMA(acc[mt][nt], al[mt][0], al[mt][1], al[mt][2], al[mt][3], b0, b1);
                    }
                }
            }
        }
        __syncthreads();
    }

    // ---- dump pre-activations to smem (overlay stage buffers) ----
    float* Ps = (float*)sm;
    int* sOrig = (int*)(sm + IDS_OFF);
    int* sNid  = sOrig + 64;
#pragma unroll
    for (int mt = 0; mt < 2; mt++) {
#pragma unroll
        for (int nt = 0; nt < 13; nt++) {
            int col = 8 * (nw + 4 * nt) + 2 * t4;
            int r1 = wm0 + mt * 16 + g;
            *(float2*)&Ps[r1 * PST + col] = make_float2(acc[mt][nt][0], acc[mt][nt][1]);
            *(float2*)&Ps[(r1 + 8) * PST + col] = make_float2(acc[mt][nt][2], acc[mt][nt][3]);
        }
    }
    if (tid < 64) {
        size_t pr = row0 + tid;
        int o = (pr < NSEL) ? g_rowmap[pr] : 0;
        sOrig[tid] = o;
        sNid[tid]  = n_id[o];
    }
    __syncthreads();

    // ---- GRU combine: 64 rows x 100 j ----
    for (int q = tid; q < 64 * MEMD; q += 256) {
        int r = q / MEMD;
        int j = q - r * MEMD;
        if (row0 + r >= NSEL) break;
        const float* P = Ps + r * PST;
        float pr = P[2 * j]       + g_bcn[2 * j];
        float pz = P[2 * j + 1]   + g_bcn[2 * j + 1];
        float pi = P[208 + j]     + g_bcn[208 + j];
        float ph = P[312 + j]     + g_bcn[312 + j];
        float rr = 1.f / (1.f + expf(-pr));
        float zz = 1.f / (1.f + expf(-pz));
        float nn = tanhf(pi + rr * ph);
        float h  = memory[(size_t)sNid[r] * MEMD + j];
        out[(size_t)sOrig[r] * MEMD + j] = (1.f - zz) * nn + zz * h;
    }
}

// ---------------- launch ----------------
extern "C" void kernel_launch(void* const* d_in, const int* in_sizes, int n_in,
                              void* d_out, int out_size) {
    const float* memory      = (const float*)d_in[0];
    const int*   last_update = (const int*)  d_in[1];
    const int*   n_id        = (const int*)  d_in[2];
    const int*   loc_s       = (const int*)  d_in[3];
    const int*   dst_s       = (const int*)  d_in[4];
    const int*   t_s         = (const int*)  d_in[5];
    const float* raw_msg_s   = (const float*)d_in[6];
    const int*   loc_d       = (const int*)  d_in[7];
    const int*   dst_d       = (const int*)  d_in[8];
    const int*   t_d         = (const int*)  d_in[9];
    const float* raw_msg_d   = (const float*)d_in[10];
    const float* time_w      = (const float*)d_in[11];
    const float* time_b      = (const float*)d_in[12];
    const float* W_ih        = (const float*)d_in[13];
    const float* W_hh        = (const float*)d_in[14];
    const float* b_ih        = (const float*)d_in[15];
    const float* b_hh        = (const float*)d_in[16];

    float* out_mem = (float*)d_out;
    float* out_lu  = (out_size >= NSEL * MEMD + NSEL) ? out_mem + (size_t)NSEL * MEMD
                                                      : nullptr;

    cudaFuncSetAttribute(k_gemm, cudaFuncAttributeMaxDynamicSharedMemorySize, SMEM_TOT);

    k_init<<<(NSEL + 255) / 256, 256>>>();
    k_aggr<<<(2 * NE + 255) / 256, 256>>>(loc_s, t_s, loc_d, t_d);
    k_part<<<(NSEL + 255) / 256, 256>>>();
    k_prep<<<(NCP * KP + 255) / 256, 256>>>(W_ih, W_hh, b_ih, b_hh);
    k_build<<<NSEL / 8, 256>>>(memory, last_update, n_id,
                               dst_s, t_s, raw_msg_s,
                               dst_d, t_d, raw_msg_d,
                               time_w, time_b, out_lu);
    k_gemm<<<(NSEL + 63) / 64, 256, SMEM_TOT>>>(memory, n_id, out_mem);
}